// round 1
// baseline (speedup 1.0000x reference)
#include <cuda_runtime.h>
#include <math.h>

// ---------------------------------------------------------------------------
// MotionNet: correlation(81) + 2x bilinear upsample + concat(115ch) +
// conv3x3(115->32)+lrelu -> BasicBlock(2x conv3x3 32->32, residual) ->
// conv3x3(32->3) -> (flows, sigmoid mask, feats)
// B=4, C=32, H=W=256, MD=4
// ---------------------------------------------------------------------------

#define BB 4
#define HH 256
#define WW 256
#define HW (HH * WW)
#define CIN0 115

// Scratch (device globals; no allocation allowed)
__device__ float g_inp[BB * CIN0 * HW];   // concat input  [4,115,256,256]
__device__ float g_h[BB * 32 * HW];       // conv0 output (post-lrelu)
__device__ float g_t[BB * 32 * HW];       // conv1 output (post-lrelu)

__device__ __forceinline__ float lrelu(float v) {
    return v >= 0.f ? v : 0.1f * v;
}

// ---------------------------------------------------------------------------
// Correlation: out[b, dy*9+dx, h, w] = lrelu( (1/32) * sum_c ref*nb_shifted )
// shift range [-4, 4] in both dims, zero pad.
// ---------------------------------------------------------------------------
__global__ __launch_bounds__(256) void corr_kernel(
    const float* __restrict__ xref, const float* __restrict__ xnb,
    float* __restrict__ inp)
{
    const int b  = blockIdx.z;
    const int h0 = blockIdx.y * 16, w0 = blockIdx.x * 16;
    const int tx = threadIdx.x, ty = threadIdx.y;
    const int tid = ty * 16 + tx;

    __shared__ float nb[8][24][24];

    float acc[81];
#pragma unroll
    for (int k = 0; k < 81; k++) acc[k] = 0.f;

    const int h = h0 + ty, w = w0 + tx;

    for (int c0 = 0; c0 < 32; c0 += 8) {
        // load 24x24 padded neighbor tile for 8 channels
        for (int i = tid; i < 8 * 24 * 24; i += 256) {
            int cc  = i / 576;
            int rem = i % 576;
            int r = rem / 24, cl = rem % 24;
            int gy = h0 - 4 + r, gx = w0 - 4 + cl;
            float v = 0.f;
            if (gy >= 0 && gy < HH && gx >= 0 && gx < WW)
                v = xnb[((b * 32 + c0 + cc) * HH + gy) * WW + gx];
            nb[cc][r][cl] = v;
        }
        __syncthreads();
#pragma unroll
        for (int cc = 0; cc < 8; cc++) {
            float r = xref[((b * 32 + c0 + cc) * HH + h) * WW + w];
#pragma unroll
            for (int dy = 0; dy < 9; dy++) {
#pragma unroll
                for (int dx = 0; dx < 9; dx++) {
                    acc[dy * 9 + dx] += r * nb[cc][ty + dy][tx + dx];
                }
            }
        }
        __syncthreads();
    }

#pragma unroll
    for (int k = 0; k < 81; k++) {
        float v = lrelu(acc[k] * (1.f / 32.f));
        inp[((b * CIN0 + k) * HH + h) * WW + w] = v;
    }
}

// ---------------------------------------------------------------------------
// Bilinear 2x upsample (half-pixel, clamp edges == align_corners=False):
//   feature [4,32,128,128] -> inp channels 81..112
//   flow    [4,2,128,128]  -> inp channels 113..114 (scaled by 2)
// ---------------------------------------------------------------------------
__global__ __launch_bounds__(256) void upsample_kernel(
    const float* __restrict__ bfeat, const float* __restrict__ bflow,
    float* __restrict__ inp)
{
    int idx = blockIdx.x * blockDim.x + threadIdx.x;
    // total = 4 * 34 * 256 * 256
    if (idx >= BB * 34 * HW) return;
    int w  = idx & 255;
    int h  = (idx >> 8) & 255;
    int ch = (idx >> 16) % 34;
    int b  = idx / (34 * HW);

    int iy = h >> 1, ix = w >> 1;
    int ya, yb, xa, xb;
    float wya, wyb, wxa, wxb;
    if ((h & 1) == 0) { ya = max(iy - 1, 0);   yb = iy; wya = 0.25f; wyb = 0.75f; }
    else              { ya = iy; yb = min(iy + 1, 127); wya = 0.75f; wyb = 0.25f; }
    if ((w & 1) == 0) { xa = max(ix - 1, 0);   xb = ix; wxa = 0.25f; wxb = 0.75f; }
    else              { xa = ix; xb = min(ix + 1, 127); wxa = 0.75f; wxb = 0.25f; }

    const float* src;
    int cs, chout;
    float scale;
    if (ch < 32) { src = bfeat; cs = ch;      chout = 81 + ch;         scale = 1.f; }
    else         { src = bflow; cs = ch - 32; chout = 113 + (ch - 32); scale = 2.f; }

    const float* p = src + ((long)b * (ch < 32 ? 32 : 2) + cs) * 128 * 128;
    float v = wya * (wxa * p[ya * 128 + xa] + wxb * p[ya * 128 + xb])
            + wyb * (wxa * p[yb * 128 + xa] + wxb * p[yb * 128 + xb]);
    inp[((b * CIN0 + chout) * HH + h) * WW + w] = v * scale;
}

// ---------------------------------------------------------------------------
// Generic direct conv3x3, SAME pad, COUT=32. One thread = one pixel, all 32
// output channels in registers. Weights staged in smem as [ck][tap][32] and
// read with broadcast float4 LDS -> FMA-bound, not LDS-bound.
// ---------------------------------------------------------------------------
template <int CIN, int CK, bool LRELU, bool RES>
__global__ __launch_bounds__(256) void conv3x3_kernel(
    const float* __restrict__ in, const float* __restrict__ wts,
    const float* __restrict__ bias, const float* __restrict__ res,
    float* __restrict__ out)
{
    const int b  = blockIdx.z;
    const int h0 = blockIdx.y * 16, w0 = blockIdx.x * 16;
    const int tx = threadIdx.x, ty = threadIdx.y;
    const int tid = ty * 16 + tx;

    __shared__ float tile[CK][18][18];
    __shared__ __align__(16) float wsm[CK][9][32];

    float acc[32];
#pragma unroll
    for (int o = 0; o < 32; o++) acc[o] = bias[o];

    const int h = h0 + ty, w = w0 + tx;

    for (int c0 = 0; c0 < CIN; c0 += CK) {
        // input halo tile
        for (int i = tid; i < CK * 18 * 18; i += 256) {
            int cc  = i / 324;
            int rem = i % 324;
            int r = rem / 18, cl = rem % 18;
            int gy = h0 - 1 + r, gx = w0 - 1 + cl;
            float v = 0.f;
            if (gy >= 0 && gy < HH && gx >= 0 && gx < WW)
                v = in[((b * CIN + c0 + cc) * HH + gy) * WW + gx];
            tile[cc][r][cl] = v;
        }
        // weights: wsm[cc][tap][o] = wts[((o*CIN + c0+cc)*9) + tap]
        for (int i = tid; i < CK * 9 * 32; i += 256) {
            int cc  = i / (9 * 32);
            int rem = i % (9 * 32);
            int tap = rem / 32;
            int o   = rem % 32;
            wsm[cc][tap][o] = wts[(o * CIN + c0 + cc) * 9 + tap];
        }
        __syncthreads();

#pragma unroll
        for (int cc = 0; cc < CK; cc++) {
#pragma unroll
            for (int tap = 0; tap < 9; tap++) {
                int ky = tap / 3, kx = tap % 3;
                float v = tile[cc][ty + ky][tx + kx];
                const float4* wp = reinterpret_cast<const float4*>(&wsm[cc][tap][0]);
#pragma unroll
                for (int o4 = 0; o4 < 8; o4++) {
                    float4 w4 = wp[o4];
                    acc[o4 * 4 + 0] += v * w4.x;
                    acc[o4 * 4 + 1] += v * w4.y;
                    acc[o4 * 4 + 2] += v * w4.z;
                    acc[o4 * 4 + 3] += v * w4.w;
                }
            }
        }
        __syncthreads();
    }

#pragma unroll
    for (int o = 0; o < 32; o++) {
        float v = acc[o];
        if (RES) v += res[((b * 32 + o) * HH + h) * WW + w];
        if (LRELU) v = lrelu(v);
        out[((b * 32 + o) * HH + h) * WW + w] = v;
    }
}

// ---------------------------------------------------------------------------
// Final conv3x3 (32 -> 3) with fused split/stack/sigmoid epilogue.
// d_out layout: flows [4,2,1,256,256] | mask [4,1,256,256] | feats [4,32,256,256]
// ---------------------------------------------------------------------------
__global__ __launch_bounds__(256) void convf_kernel(
    const float* __restrict__ feats, const float* __restrict__ wts,
    const float* __restrict__ bias, float* __restrict__ dout)
{
    const int b  = blockIdx.z;
    const int h0 = blockIdx.y * 16, w0 = blockIdx.x * 16;
    const int tx = threadIdx.x, ty = threadIdx.y;
    const int tid = ty * 16 + tx;

    __shared__ float tile[16][18][18];
    __shared__ float wsm[32][9][3];

    // weights: [3][32][3][3] -> wsm[ci][tap][o]
    for (int i = tid; i < 32 * 9 * 3; i += 256) {
        int ci  = i / 27;
        int rem = i % 27;
        int tap = rem / 3;
        int o   = rem % 3;
        wsm[ci][tap][o] = wts[(o * 32 + ci) * 9 + tap];
    }

    float acc[3] = {bias[0], bias[1], bias[2]};
    const int h = h0 + ty, w = w0 + tx;

    for (int c0 = 0; c0 < 32; c0 += 16) {
        __syncthreads();
        for (int i = tid; i < 16 * 18 * 18; i += 256) {
            int cc  = i / 324;
            int rem = i % 324;
            int r = rem / 18, cl = rem % 18;
            int gy = h0 - 1 + r, gx = w0 - 1 + cl;
            float v = 0.f;
            if (gy >= 0 && gy < HH && gx >= 0 && gx < WW)
                v = feats[((b * 32 + c0 + cc) * HH + gy) * WW + gx];
            tile[cc][r][cl] = v;
        }
        __syncthreads();
#pragma unroll
        for (int cc = 0; cc < 16; cc++) {
#pragma unroll
            for (int tap = 0; tap < 9; tap++) {
                int ky = tap / 3, kx = tap % 3;
                float v = tile[cc][ty + ky][tx + kx];
                acc[0] += v * wsm[c0 + cc][tap][0];
                acc[1] += v * wsm[c0 + cc][tap][1];
                acc[2] += v * wsm[c0 + cc][tap][2];
            }
        }
    }

    const int pix = h * WW + w;
    // flows [B,2,1,H,W]
    dout[(b * 2 + 0) * HW + pix] = acc[0];
    dout[(b * 2 + 1) * HW + pix] = acc[1];
    // mask [B,1,H,W] with sigmoid
    float m = 1.f / (1.f + expf(-acc[2]));
    dout[BB * 2 * HW + b * HW + pix] = m;
}

// ---------------------------------------------------------------------------
// Launch
// ---------------------------------------------------------------------------
extern "C" void kernel_launch(void* const* d_in, const int* in_sizes, int n_in,
                              void* d_out, int out_size)
{
    const float* x_ref     = (const float*)d_in[0];
    const float* x_nb      = (const float*)d_in[1];
    const float* base_flow = (const float*)d_in[2]; // [4,1,2,128,128] == [4,2,128,128]
    const float* base_feat = (const float*)d_in[3];
    const float* w0 = (const float*)d_in[4];
    const float* b0 = (const float*)d_in[5];
    const float* w1 = (const float*)d_in[6];
    const float* b1 = (const float*)d_in[7];
    const float* w2 = (const float*)d_in[8];
    const float* b2 = (const float*)d_in[9];
    const float* wf = (const float*)d_in[10];
    const float* bf = (const float*)d_in[11];

    float* inp; cudaGetSymbolAddress((void**)&inp, g_inp);
    float* hbuf; cudaGetSymbolAddress((void**)&hbuf, g_h);
    float* tbuf; cudaGetSymbolAddress((void**)&tbuf, g_t);

    float* out   = (float*)d_out;
    float* feats = out + (BB * 2 * HW) + (BB * 1 * HW); // feats slice of d_out

    dim3 blk(16, 16);
    dim3 grd(WW / 16, HH / 16, BB);

    corr_kernel<<<grd, blk>>>(x_ref, x_nb, inp);
    upsample_kernel<<<(BB * 34 * HW) / 256, 256>>>(base_feat, base_flow, inp);
    conv3x3_kernel<115, 5, true, false><<<grd, blk>>>(inp, w0, b0, nullptr, hbuf);
    conv3x3_kernel<32, 16, true, false><<<grd, blk>>>(hbuf, w1, b1, nullptr, tbuf);
    conv3x3_kernel<32, 16, true, true ><<<grd, blk>>>(tbuf, w2, b2, hbuf, feats);
    convf_kernel<<<grd, blk>>>(feats, wf, bf, out);
}

// round 2
// speedup vs baseline: 1.1272x; 1.1272x over previous
#include <cuda_runtime.h>
#include <math.h>

// ---------------------------------------------------------------------------
// MotionNet: correlation(81) + 2x bilinear upsample + concat(115ch) +
// conv3x3(115->32)+lrelu -> BasicBlock(2x conv3x3 32->32, residual) ->
// conv3x3(32->3) -> (flows, sigmoid mask, feats)
// B=4, C=32, H=W=256, MD=4
// ---------------------------------------------------------------------------

#define BB 4
#define HH 256
#define WW 256
#define HW (HH * WW)
#define CIN0 115

__device__ float g_inp[BB * CIN0 * HW];   // concat input  [4,115,256,256]
__device__ float g_h[BB * 32 * HW];       // conv0 output (post-lrelu)
__device__ float g_t[BB * 32 * HW];       // conv1 output (post-lrelu)

__device__ __forceinline__ float lrelu(float v) {
    return v >= 0.f ? v : 0.1f * v;
}

// ---- packed fp32x2 helpers (sm_100+) --------------------------------------
__device__ __forceinline__ unsigned long long pack2(float lo, float hi) {
    unsigned long long r;
    asm("mov.b64 %0, {%1, %2};" : "=l"(r)
        : "r"(__float_as_uint(lo)), "r"(__float_as_uint(hi)));
    return r;
}
__device__ __forceinline__ unsigned long long pack2dup(float v) {
    unsigned long long r;
    asm("mov.b64 %0, {%1, %1};" : "=l"(r) : "r"(__float_as_uint(v)));
    return r;
}
__device__ __forceinline__ void unpack2(unsigned long long v, float& lo, float& hi) {
    unsigned int a, b;
    asm("mov.b64 {%0, %1}, %2;" : "=r"(a), "=r"(b) : "l"(v));
    lo = __uint_as_float(a);
    hi = __uint_as_float(b);
}
__device__ __forceinline__ unsigned long long ffma2(
    unsigned long long a, unsigned long long b, unsigned long long c) {
    unsigned long long d;
    asm("fma.rn.f32x2 %0, %1, %2, %3;" : "=l"(d) : "l"(a), "l"(b), "l"(c));
    return d;
}

union F4U2 { float4 f4; unsigned long long u[2]; };

// ---------------------------------------------------------------------------
// Correlation: out[b, dy*9+dx, h, w] = lrelu( (1/32) * sum_c ref*nb_shifted )
// ---------------------------------------------------------------------------
__global__ __launch_bounds__(256) void corr_kernel(
    const float* __restrict__ xref, const float* __restrict__ xnb,
    float* __restrict__ inp)
{
    const int b  = blockIdx.z;
    const int h0 = blockIdx.y * 16, w0 = blockIdx.x * 16;
    const int tx = threadIdx.x, ty = threadIdx.y;
    const int tid = ty * 16 + tx;

    __shared__ float nb[8][24][24];

    float acc[81];
#pragma unroll
    for (int k = 0; k < 81; k++) acc[k] = 0.f;

    const int h = h0 + ty, w = w0 + tx;

    for (int c0 = 0; c0 < 32; c0 += 8) {
        for (int i = tid; i < 8 * 24 * 24; i += 256) {
            int cc  = i / 576;
            int rem = i % 576;
            int r = rem / 24, cl = rem % 24;
            int gy = h0 - 4 + r, gx = w0 - 4 + cl;
            float v = 0.f;
            if (gy >= 0 && gy < HH && gx >= 0 && gx < WW)
                v = xnb[((b * 32 + c0 + cc) * HH + gy) * WW + gx];
            nb[cc][r][cl] = v;
        }
        __syncthreads();
#pragma unroll
        for (int cc = 0; cc < 8; cc++) {
            float r = xref[((b * 32 + c0 + cc) * HH + h) * WW + w];
#pragma unroll
            for (int dy = 0; dy < 9; dy++) {
#pragma unroll
                for (int dx = 0; dx < 9; dx++) {
                    acc[dy * 9 + dx] += r * nb[cc][ty + dy][tx + dx];
                }
            }
        }
        __syncthreads();
    }

#pragma unroll
    for (int k = 0; k < 81; k++) {
        float v = lrelu(acc[k] * (1.f / 32.f));
        inp[((b * CIN0 + k) * HH + h) * WW + w] = v;
    }
}

// ---------------------------------------------------------------------------
// Bilinear 2x upsample (align_corners=False)
// ---------------------------------------------------------------------------
__global__ __launch_bounds__(256) void upsample_kernel(
    const float* __restrict__ bfeat, const float* __restrict__ bflow,
    float* __restrict__ inp)
{
    int idx = blockIdx.x * blockDim.x + threadIdx.x;
    if (idx >= BB * 34 * HW) return;
    int w  = idx & 255;
    int h  = (idx >> 8) & 255;
    int ch = (idx >> 16) % 34;
    int b  = idx / (34 * HW);

    int iy = h >> 1, ix = w >> 1;
    int ya, yb, xa, xb;
    float wya, wyb, wxa, wxb;
    if ((h & 1) == 0) { ya = max(iy - 1, 0);   yb = iy; wya = 0.25f; wyb = 0.75f; }
    else              { ya = iy; yb = min(iy + 1, 127); wya = 0.75f; wyb = 0.25f; }
    if ((w & 1) == 0) { xa = max(ix - 1, 0);   xb = ix; wxa = 0.25f; wxb = 0.75f; }
    else              { xa = ix; xb = min(ix + 1, 127); wxa = 0.75f; wxb = 0.25f; }

    const float* src;
    int cs, chout;
    float scale;
    if (ch < 32) { src = bfeat; cs = ch;      chout = 81 + ch;         scale = 1.f; }
    else         { src = bflow; cs = ch - 32; chout = 113 + (ch - 32); scale = 2.f; }

    const float* p = src + ((long)b * (ch < 32 ? 32 : 2) + cs) * 128 * 128;
    float v = wya * (wxa * p[ya * 128 + xa] + wxb * p[ya * 128 + xb])
            + wyb * (wxa * p[yb * 128 + xa] + wxb * p[yb * 128 + xb]);
    inp[((b * CIN0 + chout) * HH + h) * WW + w] = v * scale;
}

// ---------------------------------------------------------------------------
// Direct conv3x3, SAME pad, COUT=32, packed f32x2 FMA, 2 pixels/thread.
// Block: 256 threads (16x16), pixel tile 16 wide x 32 high (rows ty, ty+16).
// Weights staged [ck][tap][32] (float4 broadcast); per tap the 8 weight
// loads are amortized over 2 pixels.
// ---------------------------------------------------------------------------
template <int CIN, int CK, bool LRELU, bool RES>
__global__ __launch_bounds__(256, 2) void conv3x3_kernel(
    const float* __restrict__ in, const float* __restrict__ wts,
    const float* __restrict__ bias, const float* __restrict__ res,
    float* __restrict__ out)
{
    const int b  = blockIdx.z;
    const int h0 = blockIdx.y * 32, w0 = blockIdx.x * 16;
    const int tx = threadIdx.x, ty = threadIdx.y;
    const int tid = ty * 16 + tx;

    __shared__ float tile[CK][34][18];
    __shared__ __align__(16) float wsm[CK][9][32];

    unsigned long long accA[16], accB[16];
#pragma unroll
    for (int p = 0; p < 16; p++) {
        unsigned long long bv = pack2(bias[2 * p], bias[2 * p + 1]);
        accA[p] = bv;
        accB[p] = bv;
    }

    const int hA = h0 + ty, hB = h0 + ty + 16, w = w0 + tx;

    for (int c0 = 0; c0 < CIN; c0 += CK) {
        // input halo tile (34 rows x 18 cols per channel)
        for (int i = tid; i < CK * 34 * 18; i += 256) {
            int cc  = i / (34 * 18);
            int rem = i % (34 * 18);
            int r = rem / 18, cl = rem % 18;
            int gy = h0 - 1 + r, gx = w0 - 1 + cl;
            float v = 0.f;
            if (gy >= 0 && gy < HH && gx >= 0 && gx < WW)
                v = in[((b * CIN + c0 + cc) * HH + gy) * WW + gx];
            tile[cc][r][cl] = v;
        }
        // weights: wsm[cc][tap][o] = wts[(o*CIN + c0+cc)*9 + tap]
        for (int i = tid; i < CK * 9 * 32; i += 256) {
            int cc  = i / (9 * 32);
            int rem = i % (9 * 32);
            int tap = rem / 32;
            int o   = rem % 32;
            wsm[cc][tap][o] = wts[(o * CIN + c0 + cc) * 9 + tap];
        }
        __syncthreads();

        for (int cc = 0; cc < CK; cc++) {   // intentionally not unrolled (I$)
#pragma unroll
            for (int ky = 0; ky < 3; ky++) {
#pragma unroll
                for (int kx = 0; kx < 3; kx++) {
                    const int tap = ky * 3 + kx;
                    unsigned long long va = pack2dup(tile[cc][ty + ky][tx + kx]);
                    unsigned long long vb = pack2dup(tile[cc][ty + 16 + ky][tx + kx]);
                    const F4U2* wp = reinterpret_cast<const F4U2*>(&wsm[cc][tap][0]);
#pragma unroll
                    for (int q = 0; q < 8; q++) {
                        F4U2 wv = wp[q];
                        accA[q * 2 + 0] = ffma2(va, wv.u[0], accA[q * 2 + 0]);
                        accA[q * 2 + 1] = ffma2(va, wv.u[1], accA[q * 2 + 1]);
                        accB[q * 2 + 0] = ffma2(vb, wv.u[0], accB[q * 2 + 0]);
                        accB[q * 2 + 1] = ffma2(vb, wv.u[1], accB[q * 2 + 1]);
                    }
                }
            }
        }
        __syncthreads();
    }

#pragma unroll
    for (int p = 0; p < 16; p++) {
        float a0, a1, b0v, b1v;
        unpack2(accA[p], a0, a1);
        unpack2(accB[p], b0v, b1v);
        const int o0 = 2 * p, o1 = 2 * p + 1;
        long baseA0 = ((long)(b * 32 + o0) * HH + hA) * WW + w;
        long baseA1 = ((long)(b * 32 + o1) * HH + hA) * WW + w;
        long baseB0 = ((long)(b * 32 + o0) * HH + hB) * WW + w;
        long baseB1 = ((long)(b * 32 + o1) * HH + hB) * WW + w;
        if (RES) {
            a0  += res[baseA0]; a1  += res[baseA1];
            b0v += res[baseB0]; b1v += res[baseB1];
        }
        if (LRELU) {
            a0 = lrelu(a0); a1 = lrelu(a1);
            b0v = lrelu(b0v); b1v = lrelu(b1v);
        }
        out[baseA0] = a0;  out[baseA1] = a1;
        out[baseB0] = b0v; out[baseB1] = b1v;
    }
}

// ---------------------------------------------------------------------------
// Final conv3x3 (32 -> 3) with fused split/stack/sigmoid epilogue.
// d_out layout: flows [4,2,1,256,256] | mask [4,1,256,256] | feats [4,32,256,256]
// ---------------------------------------------------------------------------
__global__ __launch_bounds__(256) void convf_kernel(
    const float* __restrict__ feats, const float* __restrict__ wts,
    const float* __restrict__ bias, float* __restrict__ dout)
{
    const int b  = blockIdx.z;
    const int h0 = blockIdx.y * 16, w0 = blockIdx.x * 16;
    const int tx = threadIdx.x, ty = threadIdx.y;
    const int tid = ty * 16 + tx;

    __shared__ float tile[16][18][18];
    __shared__ float wsm[32][9][3];

    for (int i = tid; i < 32 * 9 * 3; i += 256) {
        int ci  = i / 27;
        int rem = i % 27;
        int tap = rem / 3;
        int o   = rem % 3;
        wsm[ci][tap][o] = wts[(o * 32 + ci) * 9 + tap];
    }

    float acc[3] = {bias[0], bias[1], bias[2]};
    const int h = h0 + ty, w = w0 + tx;

    for (int c0 = 0; c0 < 32; c0 += 16) {
        __syncthreads();
        for (int i = tid; i < 16 * 18 * 18; i += 256) {
            int cc  = i / 324;
            int rem = i % 324;
            int r = rem / 18, cl = rem % 18;
            int gy = h0 - 1 + r, gx = w0 - 1 + cl;
            float v = 0.f;
            if (gy >= 0 && gy < HH && gx >= 0 && gx < WW)
                v = feats[((b * 32 + c0 + cc) * HH + gy) * WW + gx];
            tile[cc][r][cl] = v;
        }
        __syncthreads();
#pragma unroll
        for (int cc = 0; cc < 16; cc++) {
#pragma unroll
            for (int tap = 0; tap < 9; tap++) {
                int ky = tap / 3, kx = tap % 3;
                float v = tile[cc][ty + ky][tx + kx];
                acc[0] += v * wsm[c0 + cc][tap][0];
                acc[1] += v * wsm[c0 + cc][tap][1];
                acc[2] += v * wsm[c0 + cc][tap][2];
            }
        }
    }

    const int pix = h * WW + w;
    dout[(b * 2 + 0) * HW + pix] = acc[0];
    dout[(b * 2 + 1) * HW + pix] = acc[1];
    float m = 1.f / (1.f + expf(-acc[2]));
    dout[BB * 2 * HW + b * HW + pix] = m;
}

// ---------------------------------------------------------------------------
// Launch
// ---------------------------------------------------------------------------
extern "C" void kernel_launch(void* const* d_in, const int* in_sizes, int n_in,
                              void* d_out, int out_size)
{
    const float* x_ref     = (const float*)d_in[0];
    const float* x_nb      = (const float*)d_in[1];
    const float* base_flow = (const float*)d_in[2];
    const float* base_feat = (const float*)d_in[3];
    const float* w0 = (const float*)d_in[4];
    const float* b0 = (const float*)d_in[5];
    const float* w1 = (const float*)d_in[6];
    const float* b1 = (const float*)d_in[7];
    const float* w2 = (const float*)d_in[8];
    const float* b2 = (const float*)d_in[9];
    const float* wf = (const float*)d_in[10];
    const float* bf = (const float*)d_in[11];

    float* inp;  cudaGetSymbolAddress((void**)&inp, g_inp);
    float* hbuf; cudaGetSymbolAddress((void**)&hbuf, g_h);
    float* tbuf; cudaGetSymbolAddress((void**)&tbuf, g_t);

    float* out   = (float*)d_out;
    float* feats = out + (BB * 2 * HW) + (BB * 1 * HW);

    dim3 blk(16, 16);
    dim3 grd16(WW / 16, HH / 16, BB);   // 16x16 pixel tiles
    dim3 grd32(WW / 16, HH / 32, BB);   // 16x32 pixel tiles (conv)

    corr_kernel<<<grd16, blk>>>(x_ref, x_nb, inp);
    upsample_kernel<<<(BB * 34 * HW) / 256, 256>>>(base_feat, base_flow, inp);
    conv3x3_kernel<115, 5, true, false><<<grd32, blk>>>(inp, w0, b0, nullptr, hbuf);
    conv3x3_kernel<32, 8, true, false><<<grd32, blk>>>(hbuf, w1, b1, nullptr, tbuf);
    conv3x3_kernel<32, 8, true, true ><<<grd32, blk>>>(tbuf, w2, b2, hbuf, feats);
    convf_kernel<<<grd16, blk>>>(feats, wf, bf, out);
}

// round 3
// speedup vs baseline: 1.3064x; 1.1589x over previous
#include <cuda_runtime.h>
#include <math.h>

// ---------------------------------------------------------------------------
// MotionNet: correlation(81) + 2x bilinear upsample + concat(115ch) +
// conv3x3(115->32)+lrelu -> BasicBlock(2x conv3x3 32->32, residual) ->
// conv3x3(32->3) -> (flows, sigmoid mask, feats)
// B=4, C=32, H=W=256, MD=4
// ---------------------------------------------------------------------------

#define BB 4
#define HH 256
#define WW 256
#define HW (HH * WW)
#define CIN0 115

__device__ float g_inp[BB * CIN0 * HW];   // concat input  [4,115,256,256]
__device__ float g_h[BB * 32 * HW];       // conv0 output (post-lrelu)
__device__ float g_t[BB * 32 * HW];       // conv1 output (post-lrelu)

__device__ __forceinline__ float lrelu(float v) {
    return v >= 0.f ? v : 0.1f * v;
}

// ---- packed fp32x2 helpers (sm_100+) --------------------------------------
__device__ __forceinline__ unsigned long long pack2(float lo, float hi) {
    unsigned long long r;
    asm("mov.b64 %0, {%1, %2};" : "=l"(r)
        : "r"(__float_as_uint(lo)), "r"(__float_as_uint(hi)));
    return r;
}
__device__ __forceinline__ unsigned long long pack2dup(float v) {
    unsigned long long r;
    asm("mov.b64 %0, {%1, %1};" : "=l"(r) : "r"(__float_as_uint(v)));
    return r;
}
__device__ __forceinline__ void unpack2(unsigned long long v, float& lo, float& hi) {
    unsigned int a, b;
    asm("mov.b64 {%0, %1}, %2;" : "=r"(a), "=r"(b) : "l"(v));
    lo = __uint_as_float(a);
    hi = __uint_as_float(b);
}
__device__ __forceinline__ unsigned long long ffma2(
    unsigned long long a, unsigned long long b, unsigned long long c) {
    unsigned long long d;
    asm("fma.rn.f32x2 %0, %1, %2, %3;" : "=l"(d) : "l"(a), "l"(b), "l"(c));
    return d;
}

union F4U2 { float4 f4; unsigned long long u[2]; };

// ---- cp.async helpers ------------------------------------------------------
__device__ __forceinline__ unsigned smem_u32(const void* p) {
    return (unsigned)__cvta_generic_to_shared(p);
}
__device__ __forceinline__ void cp_async4(unsigned dst, const float* src, bool pred) {
    int sz = pred ? 4 : 0;
    asm volatile("cp.async.ca.shared.global [%0], [%1], 4, %2;"
                 :: "r"(dst), "l"(src), "r"(sz));
}
__device__ __forceinline__ void cp_commit() {
    asm volatile("cp.async.commit_group;");
}
__device__ __forceinline__ void cp_wait0() {
    asm volatile("cp.async.wait_group 0;");
}

// ---------------------------------------------------------------------------
// Correlation
// ---------------------------------------------------------------------------
__global__ __launch_bounds__(256) void corr_kernel(
    const float* __restrict__ xref, const float* __restrict__ xnb,
    float* __restrict__ inp)
{
    const int b  = blockIdx.z;
    const int h0 = blockIdx.y * 16, w0 = blockIdx.x * 16;
    const int tx = threadIdx.x, ty = threadIdx.y;
    const int tid = ty * 16 + tx;

    __shared__ float nb[8][24][24];

    float acc[81];
#pragma unroll
    for (int k = 0; k < 81; k++) acc[k] = 0.f;

    const int h = h0 + ty, w = w0 + tx;

    for (int c0 = 0; c0 < 32; c0 += 8) {
        for (int i = tid; i < 8 * 24 * 24; i += 256) {
            int cc  = i / 576;
            int rem = i % 576;
            int r = rem / 24, cl = rem % 24;
            int gy = h0 - 4 + r, gx = w0 - 4 + cl;
            float v = 0.f;
            if (gy >= 0 && gy < HH && gx >= 0 && gx < WW)
                v = xnb[((b * 32 + c0 + cc) * HH + gy) * WW + gx];
            nb[cc][r][cl] = v;
        }
        __syncthreads();
#pragma unroll
        for (int cc = 0; cc < 8; cc++) {
            float r = xref[((b * 32 + c0 + cc) * HH + h) * WW + w];
#pragma unroll
            for (int dy = 0; dy < 9; dy++) {
#pragma unroll
                for (int dx = 0; dx < 9; dx++) {
                    acc[dy * 9 + dx] += r * nb[cc][ty + dy][tx + dx];
                }
            }
        }
        __syncthreads();
    }

#pragma unroll
    for (int k = 0; k < 81; k++) {
        float v = lrelu(acc[k] * (1.f / 32.f));
        inp[((b * CIN0 + k) * HH + h) * WW + w] = v;
    }
}

// ---------------------------------------------------------------------------
// Bilinear 2x upsample (align_corners=False)
// ---------------------------------------------------------------------------
__global__ __launch_bounds__(256) void upsample_kernel(
    const float* __restrict__ bfeat, const float* __restrict__ bflow,
    float* __restrict__ inp)
{
    int idx = blockIdx.x * blockDim.x + threadIdx.x;
    if (idx >= BB * 34 * HW) return;
    int w  = idx & 255;
    int h  = (idx >> 8) & 255;
    int ch = (idx >> 16) % 34;
    int b  = idx / (34 * HW);

    int iy = h >> 1, ix = w >> 1;
    int ya, yb, xa, xb;
    float wya, wyb, wxa, wxb;
    if ((h & 1) == 0) { ya = max(iy - 1, 0);   yb = iy; wya = 0.25f; wyb = 0.75f; }
    else              { ya = iy; yb = min(iy + 1, 127); wya = 0.75f; wyb = 0.25f; }
    if ((w & 1) == 0) { xa = max(ix - 1, 0);   xb = ix; wxa = 0.25f; wxb = 0.75f; }
    else              { xa = ix; xb = min(ix + 1, 127); wxa = 0.75f; wxb = 0.25f; }

    const float* src;
    int cs, chout;
    float scale;
    if (ch < 32) { src = bfeat; cs = ch;      chout = 81 + ch;         scale = 1.f; }
    else         { src = bflow; cs = ch - 32; chout = 113 + (ch - 32); scale = 2.f; }

    const float* p = src + ((long)b * (ch < 32 ? 32 : 2) + cs) * 128 * 128;
    float v = wya * (wxa * p[ya * 128 + xa] + wxb * p[ya * 128 + xb])
            + wyb * (wxa * p[yb * 128 + xa] + wxb * p[yb * 128 + xb]);
    inp[((b * CIN0 + chout) * HH + h) * WW + w] = v * scale;
}

// ---------------------------------------------------------------------------
// conv3x3 32->32: ALL weights resident in smem (36KB), input tiles
// double-buffered via cp.async. 2 pixels/thread (rows ty, ty+16), f32x2 FMA.
// Dynamic smem: wall[32*9*32] + tiles[2][8*34*18]  = 76,032 B
// ---------------------------------------------------------------------------
#define C32_CK 8
#define C32_TILE (C32_CK * 34 * 18)        // 4896
#define C32_WALL (32 * 9 * 32)             // 9216
#define C32_SMEM ((C32_WALL + 2 * C32_TILE) * 4)

template <bool RES, bool LRELU_OUT>
__global__ __launch_bounds__(256, 2) void conv32_kernel(
    const float* __restrict__ in, const float* __restrict__ wts,
    const float* __restrict__ bias, const float* __restrict__ res,
    float* __restrict__ out)
{
    extern __shared__ float smem[];
    float* wall  = smem;                 // [ci][tap][o] -> 32*9*32
    float* tiles = smem + C32_WALL;      // 2 buffers of [cc][34][18]

    const int b  = blockIdx.z;
    const int h0 = blockIdx.y * 32, w0 = blockIdx.x * 16;
    const int tx = threadIdx.x, ty = threadIdx.y;
    const int tid = ty * 16 + tx;

    // --- prologue: async-load all weights (transposed) + tile chunk 0 ------
    for (int i = tid; i < C32_WALL; i += 256) {
        int ci  = i / 288;
        int rem = i % 288;
        int tap = rem / 32;
        int o   = rem % 32;
        cp_async4(smem_u32(&wall[i]), wts + (o * 32 + ci) * 9 + tap, true);
    }
    {
        float* t0 = tiles;
        for (int i = tid; i < C32_TILE; i += 256) {
            int cc  = i / 612;
            int rem = i % 612;
            int r = rem / 18, cl = rem % 18;
            int gy = h0 - 1 + r, gx = w0 - 1 + cl;
            bool ok = (gy >= 0 && gy < HH && gx >= 0 && gx < WW);
            const float* src = in + (((long)(b * 32 + cc) * HH + (ok ? gy : 0)) * WW + (ok ? gx : 0));
            cp_async4(smem_u32(&t0[i]), src, ok);
        }
    }
    cp_commit();

    unsigned long long accA[16], accB[16];
#pragma unroll
    for (int p = 0; p < 16; p++) {
        unsigned long long bv = pack2(bias[2 * p], bias[2 * p + 1]);
        accA[p] = bv;
        accB[p] = bv;
    }

    const int hA = h0 + ty, hB = h0 + ty + 16, w = w0 + tx;

    cp_wait0();
    __syncthreads();

    for (int chunk = 0; chunk < 4; chunk++) {
        const int c0 = chunk * C32_CK;
        float* cur = tiles + (chunk & 1) * C32_TILE;
        // prefetch next chunk
        if (chunk < 3) {
            float* nxt = tiles + ((chunk + 1) & 1) * C32_TILE;
            const int cn = (chunk + 1) * C32_CK;
            for (int i = tid; i < C32_TILE; i += 256) {
                int cc  = i / 612;
                int rem = i % 612;
                int r = rem / 18, cl = rem % 18;
                int gy = h0 - 1 + r, gx = w0 - 1 + cl;
                bool ok = (gy >= 0 && gy < HH && gx >= 0 && gx < WW);
                const float* src = in + (((long)(b * 32 + cn + cc) * HH + (ok ? gy : 0)) * WW + (ok ? gx : 0));
                cp_async4(smem_u32(&nxt[i]), src, ok);
            }
        }
        cp_commit();

#pragma unroll 2
        for (int cc = 0; cc < C32_CK; cc++) {
            const float* tbase = cur + cc * 612;
#pragma unroll
            for (int ky = 0; ky < 3; ky++) {
#pragma unroll
                for (int kx = 0; kx < 3; kx++) {
                    const int tap = ky * 3 + kx;
                    unsigned long long va = pack2dup(tbase[(ty + ky) * 18 + tx + kx]);
                    unsigned long long vb = pack2dup(tbase[(ty + 16 + ky) * 18 + tx + kx]);
                    const F4U2* wp = reinterpret_cast<const F4U2*>(
                        wall + ((c0 + cc) * 9 + tap) * 32);
#pragma unroll
                    for (int q = 0; q < 8; q++) {
                        F4U2 wv = wp[q];
                        accA[q * 2 + 0] = ffma2(va, wv.u[0], accA[q * 2 + 0]);
                        accA[q * 2 + 1] = ffma2(va, wv.u[1], accA[q * 2 + 1]);
                        accB[q * 2 + 0] = ffma2(vb, wv.u[0], accB[q * 2 + 0]);
                        accB[q * 2 + 1] = ffma2(vb, wv.u[1], accB[q * 2 + 1]);
                    }
                }
            }
        }

        cp_wait0();
        __syncthreads();
    }

#pragma unroll
    for (int p = 0; p < 16; p++) {
        float a0, a1, b0v, b1v;
        unpack2(accA[p], a0, a1);
        unpack2(accB[p], b0v, b1v);
        const int o0 = 2 * p, o1 = 2 * p + 1;
        long baseA0 = ((long)(b * 32 + o0) * HH + hA) * WW + w;
        long baseA1 = ((long)(b * 32 + o1) * HH + hA) * WW + w;
        long baseB0 = ((long)(b * 32 + o0) * HH + hB) * WW + w;
        long baseB1 = ((long)(b * 32 + o1) * HH + hB) * WW + w;
        if (RES) {
            a0  += res[baseA0]; a1  += res[baseA1];
            b0v += res[baseB0]; b1v += res[baseB1];
        }
        if (LRELU_OUT) {
            a0 = lrelu(a0); a1 = lrelu(a1);
            b0v = lrelu(b0v); b1v = lrelu(b1v);
        }
        out[baseA0] = a0;  out[baseA1] = a1;
        out[baseB0] = b0v; out[baseB1] = b1v;
    }
}

// ---------------------------------------------------------------------------
// conv0: 115 -> 32. Double-buffered tiles AND weight stages (CK=5), cp.async.
// Static smem: 2*(5*34*18) + 2*(5*9*32) = 9000 floats = 36 KB
// ---------------------------------------------------------------------------
#define C0_CK 5
#define C0_TILE (C0_CK * 34 * 18)          // 3060
#define C0_WCHK (C0_CK * 9 * 32)           // 1440

__global__ __launch_bounds__(256, 2) void conv0_kernel(
    const float* __restrict__ in, const float* __restrict__ wts,
    const float* __restrict__ bias, float* __restrict__ out)
{
    __shared__ __align__(16) float tiles[2][C0_TILE];
    __shared__ __align__(16) float wbuf[2][C0_WCHK];

    const int b  = blockIdx.z;
    const int h0 = blockIdx.y * 32, w0 = blockIdx.x * 16;
    const int tx = threadIdx.x, ty = threadIdx.y;
    const int tid = ty * 16 + tx;

    // prologue: chunk 0 tile + weights
    for (int i = tid; i < C0_TILE; i += 256) {
        int cc  = i / 612;
        int rem = i % 612;
        int r = rem / 18, cl = rem % 18;
        int gy = h0 - 1 + r, gx = w0 - 1 + cl;
        bool ok = (gy >= 0 && gy < HH && gx >= 0 && gx < WW);
        const float* src = in + (((long)(b * CIN0 + cc) * HH + (ok ? gy : 0)) * WW + (ok ? gx : 0));
        cp_async4(smem_u32(&tiles[0][i]), src, ok);
    }
    for (int i = tid; i < C0_WCHK; i += 256) {
        int cc  = i / 288;
        int rem = i % 288;
        int tap = rem / 32;
        int o   = rem % 32;
        cp_async4(smem_u32(&wbuf[0][i]), wts + (o * CIN0 + cc) * 9 + tap, true);
    }
    cp_commit();

    unsigned long long accA[16], accB[16];
#pragma unroll
    for (int p = 0; p < 16; p++) {
        unsigned long long bv = pack2(bias[2 * p], bias[2 * p + 1]);
        accA[p] = bv;
        accB[p] = bv;
    }

    const int hA = h0 + ty, hB = h0 + ty + 16, w = w0 + tx;

    cp_wait0();
    __syncthreads();

    for (int chunk = 0; chunk < 23; chunk++) {
        const float* cur = tiles[chunk & 1];
        const float* wc  = wbuf[chunk & 1];
        if (chunk < 22) {
            float* nt = tiles[(chunk + 1) & 1];
            float* nw = wbuf[(chunk + 1) & 1];
            const int cn = (chunk + 1) * C0_CK;
            for (int i = tid; i < C0_TILE; i += 256) {
                int cc  = i / 612;
                int rem = i % 612;
                int r = rem / 18, cl = rem % 18;
                int gy = h0 - 1 + r, gx = w0 - 1 + cl;
                bool ok = (gy >= 0 && gy < HH && gx >= 0 && gx < WW);
                const float* src = in + (((long)(b * CIN0 + cn + cc) * HH + (ok ? gy : 0)) * WW + (ok ? gx : 0));
                cp_async4(smem_u32(&nt[i]), src, ok);
            }
            for (int i = tid; i < C0_WCHK; i += 256) {
                int cc  = i / 288;
                int rem = i % 288;
                int tap = rem / 32;
                int o   = rem % 32;
                cp_async4(smem_u32(&nw[i]), wts + (o * CIN0 + cn + cc) * 9 + tap, true);
            }
        }
        cp_commit();

#pragma unroll
        for (int cc = 0; cc < C0_CK; cc++) {
            const float* tbase = cur + cc * 612;
#pragma unroll
            for (int ky = 0; ky < 3; ky++) {
#pragma unroll
                for (int kx = 0; kx < 3; kx++) {
                    const int tap = ky * 3 + kx;
                    unsigned long long va = pack2dup(tbase[(ty + ky) * 18 + tx + kx]);
                    unsigned long long vb = pack2dup(tbase[(ty + 16 + ky) * 18 + tx + kx]);
                    const F4U2* wp = reinterpret_cast<const F4U2*>(
                        wc + (cc * 9 + tap) * 32);
#pragma unroll
                    for (int q = 0; q < 8; q++) {
                        F4U2 wv = wp[q];
                        accA[q * 2 + 0] = ffma2(va, wv.u[0], accA[q * 2 + 0]);
                        accA[q * 2 + 1] = ffma2(va, wv.u[1], accA[q * 2 + 1]);
                        accB[q * 2 + 0] = ffma2(vb, wv.u[0], accB[q * 2 + 0]);
                        accB[q * 2 + 1] = ffma2(vb, wv.u[1], accB[q * 2 + 1]);
                    }
                }
            }
        }

        cp_wait0();
        __syncthreads();
    }

#pragma unroll
    for (int p = 0; p < 16; p++) {
        float a0, a1, b0v, b1v;
        unpack2(accA[p], a0, a1);
        unpack2(accB[p], b0v, b1v);
        const int o0 = 2 * p, o1 = 2 * p + 1;
        long baseA0 = ((long)(b * 32 + o0) * HH + hA) * WW + w;
        long baseA1 = ((long)(b * 32 + o1) * HH + hA) * WW + w;
        long baseB0 = ((long)(b * 32 + o0) * HH + hB) * WW + w;
        long baseB1 = ((long)(b * 32 + o1) * HH + hB) * WW + w;
        out[baseA0] = lrelu(a0);  out[baseA1] = lrelu(a1);
        out[baseB0] = lrelu(b0v); out[baseB1] = lrelu(b1v);
    }
}

// ---------------------------------------------------------------------------
// Final conv3x3 (32 -> 3) with fused split/stack/sigmoid epilogue.
// ---------------------------------------------------------------------------
__global__ __launch_bounds__(256) void convf_kernel(
    const float* __restrict__ feats, const float* __restrict__ wts,
    const float* __restrict__ bias, float* __restrict__ dout)
{
    const int b  = blockIdx.z;
    const int h0 = blockIdx.y * 16, w0 = blockIdx.x * 16;
    const int tx = threadIdx.x, ty = threadIdx.y;
    const int tid = ty * 16 + tx;

    __shared__ float tile[16][18][18];
    __shared__ float wsm[32][9][3];

    for (int i = tid; i < 32 * 9 * 3; i += 256) {
        int ci  = i / 27;
        int rem = i % 27;
        int tap = rem / 3;
        int o   = rem % 3;
        wsm[ci][tap][o] = wts[(o * 32 + ci) * 9 + tap];
    }

    float acc[3] = {bias[0], bias[1], bias[2]};
    const int h = h0 + ty, w = w0 + tx;

    for (int c0 = 0; c0 < 32; c0 += 16) {
        __syncthreads();
        for (int i = tid; i < 16 * 18 * 18; i += 256) {
            int cc  = i / 324;
            int rem = i % 324;
            int r = rem / 18, cl = rem % 18;
            int gy = h0 - 1 + r, gx = w0 - 1 + cl;
            float v = 0.f;
            if (gy >= 0 && gy < HH && gx >= 0 && gx < WW)
                v = feats[((b * 32 + c0 + cc) * HH + gy) * WW + gx];
            tile[cc][r][cl] = v;
        }
        __syncthreads();
#pragma unroll
        for (int cc = 0; cc < 16; cc++) {
#pragma unroll
            for (int tap = 0; tap < 9; tap++) {
                int ky = tap / 3, kx = tap % 3;
                float v = tile[cc][ty + ky][tx + kx];
                acc[0] += v * wsm[c0 + cc][tap][0];
                acc[1] += v * wsm[c0 + cc][tap][1];
                acc[2] += v * wsm[c0 + cc][tap][2];
            }
        }
    }

    const int pix = h * WW + w;
    dout[(b * 2 + 0) * HW + pix] = acc[0];
    dout[(b * 2 + 1) * HW + pix] = acc[1];
    float m = 1.f / (1.f + expf(-acc[2]));
    dout[BB * 2 * HW + b * HW + pix] = m;
}

// ---------------------------------------------------------------------------
// Launch
// ---------------------------------------------------------------------------
extern "C" void kernel_launch(void* const* d_in, const int* in_sizes, int n_in,
                              void* d_out, int out_size)
{
    const float* x_ref     = (const float*)d_in[0];
    const float* x_nb      = (const float*)d_in[1];
    const float* base_flow = (const float*)d_in[2];
    const float* base_feat = (const float*)d_in[3];
    const float* w0 = (const float*)d_in[4];
    const float* b0 = (const float*)d_in[5];
    const float* w1 = (const float*)d_in[6];
    const float* b1 = (const float*)d_in[7];
    const float* w2 = (const float*)d_in[8];
    const float* b2 = (const float*)d_in[9];
    const float* wf = (const float*)d_in[10];
    const float* bf = (const float*)d_in[11];

    float* inp;  cudaGetSymbolAddress((void**)&inp, g_inp);
    float* hbuf; cudaGetSymbolAddress((void**)&hbuf, g_h);
    float* tbuf; cudaGetSymbolAddress((void**)&tbuf, g_t);

    float* out   = (float*)d_out;
    float* feats = out + (BB * 2 * HW) + (BB * 1 * HW);

    cudaFuncSetAttribute(conv32_kernel<false, true>,
                         cudaFuncAttributeMaxDynamicSharedMemorySize, C32_SMEM);
    cudaFuncSetAttribute(conv32_kernel<true, true>,
                         cudaFuncAttributeMaxDynamicSharedMemorySize, C32_SMEM);

    dim3 blk(16, 16);
    dim3 grd16(WW / 16, HH / 16, BB);   // 16x16 pixel tiles
    dim3 grd32(WW / 16, HH / 32, BB);   // 16x32 pixel tiles (conv)

    corr_kernel<<<grd16, blk>>>(x_ref, x_nb, inp);
    upsample_kernel<<<(BB * 34 * HW) / 256, 256>>>(base_feat, base_flow, inp);
    conv0_kernel<<<grd32, blk>>>(inp, w0, b0, hbuf);
    conv32_kernel<false, true><<<grd32, blk, C32_SMEM>>>(hbuf, w1, b1, nullptr, tbuf);
    conv32_kernel<true,  true><<<grd32, blk, C32_SMEM>>>(tbuf, w2, b2, hbuf, feats);
    convf_kernel<<<grd16, blk>>>(feats, wf, bf, out);
}

// round 4
// speedup vs baseline: 1.3065x; 1.0001x over previous
#include <cuda_runtime.h>
#include <math.h>

// ---------------------------------------------------------------------------
// MotionNet: correlation(81) + 2x bilinear upsample + concat(115ch) +
// conv3x3(115->32)+lrelu -> BasicBlock(2x conv3x3 32->32, residual) ->
// conv3x3(32->3) -> (flows, sigmoid mask, feats)
// B=4, C=32, H=W=256, MD=4
// ---------------------------------------------------------------------------

#define BB 4
#define HH 256
#define WW 256
#define HW (HH * WW)
#define CIN0 115

__device__ float g_inp[BB * CIN0 * HW];   // concat input  [4,115,256,256]
__device__ float g_h[BB * 32 * HW];       // conv0 output (post-lrelu)
__device__ float g_t[BB * 32 * HW];       // conv1 output (post-lrelu)

__device__ __forceinline__ float lrelu(float v) {
    return v >= 0.f ? v : 0.1f * v;
}

// ---- packed fp32x2 helpers (sm_100+) --------------------------------------
__device__ __forceinline__ unsigned long long pack2(float lo, float hi) {
    unsigned long long r;
    asm("mov.b64 %0, {%1, %2};" : "=l"(r)
        : "r"(__float_as_uint(lo)), "r"(__float_as_uint(hi)));
    return r;
}
__device__ __forceinline__ unsigned long long pack2dup(float v) {
    unsigned long long r;
    asm("mov.b64 %0, {%1, %1};" : "=l"(r) : "r"(__float_as_uint(v)));
    return r;
}
__device__ __forceinline__ void unpack2(unsigned long long v, float& lo, float& hi) {
    unsigned int a, b;
    asm("mov.b64 {%0, %1}, %2;" : "=r"(a), "=r"(b) : "l"(v));
    lo = __uint_as_float(a);
    hi = __uint_as_float(b);
}
__device__ __forceinline__ unsigned long long ffma2(
    unsigned long long a, unsigned long long b, unsigned long long c) {
    unsigned long long d;
    asm("fma.rn.f32x2 %0, %1, %2, %3;" : "=l"(d) : "l"(a), "l"(b), "l"(c));
    return d;
}

union F4U2 { float4 f4; unsigned long long u[2]; };

// ---- cp.async helpers ------------------------------------------------------
__device__ __forceinline__ unsigned smem_u32(const void* p) {
    return (unsigned)__cvta_generic_to_shared(p);
}
__device__ __forceinline__ void cp_async4(unsigned dst, const float* src, bool pred) {
    int sz = pred ? 4 : 0;
    asm volatile("cp.async.ca.shared.global [%0], [%1], 4, %2;"
                 :: "r"(dst), "l"(src), "r"(sz));
}
__device__ __forceinline__ void cp_commit() {
    asm volatile("cp.async.commit_group;");
}
__device__ __forceinline__ void cp_wait0() {
    asm volatile("cp.async.wait_group 0;");
}

// ---------------------------------------------------------------------------
// Correlation
// ---------------------------------------------------------------------------
__global__ __launch_bounds__(256) void corr_kernel(
    const float* __restrict__ xref, const float* __restrict__ xnb,
    float* __restrict__ inp)
{
    const int b  = blockIdx.z;
    const int h0 = blockIdx.y * 16, w0 = blockIdx.x * 16;
    const int tx = threadIdx.x, ty = threadIdx.y;
    const int tid = ty * 16 + tx;

    __shared__ float nb[8][24][24];

    float acc[81];
#pragma unroll
    for (int k = 0; k < 81; k++) acc[k] = 0.f;

    const int h = h0 + ty, w = w0 + tx;

    for (int c0 = 0; c0 < 32; c0 += 8) {
        for (int i = tid; i < 8 * 24 * 24; i += 256) {
            int cc  = i / 576;
            int rem = i % 576;
            int r = rem / 24, cl = rem % 24;
            int gy = h0 - 4 + r, gx = w0 - 4 + cl;
            float v = 0.f;
            if (gy >= 0 && gy < HH && gx >= 0 && gx < WW)
                v = xnb[((b * 32 + c0 + cc) * HH + gy) * WW + gx];
            nb[cc][r][cl] = v;
        }
        __syncthreads();
#pragma unroll
        for (int cc = 0; cc < 8; cc++) {
            float r = xref[((b * 32 + c0 + cc) * HH + h) * WW + w];
#pragma unroll
            for (int dy = 0; dy < 9; dy++) {
#pragma unroll
                for (int dx = 0; dx < 9; dx++) {
                    acc[dy * 9 + dx] += r * nb[cc][ty + dy][tx + dx];
                }
            }
        }
        __syncthreads();
    }

#pragma unroll
    for (int k = 0; k < 81; k++) {
        float v = lrelu(acc[k] * (1.f / 32.f));
        inp[((b * CIN0 + k) * HH + h) * WW + w] = v;
    }
}

// ---------------------------------------------------------------------------
// Bilinear 2x upsample (align_corners=False)
// ---------------------------------------------------------------------------
__global__ __launch_bounds__(256) void upsample_kernel(
    const float* __restrict__ bfeat, const float* __restrict__ bflow,
    float* __restrict__ inp)
{
    int idx = blockIdx.x * blockDim.x + threadIdx.x;
    if (idx >= BB * 34 * HW) return;
    int w  = idx & 255;
    int h  = (idx >> 8) & 255;
    int ch = (idx >> 16) % 34;
    int b  = idx / (34 * HW);

    int iy = h >> 1, ix = w >> 1;
    int ya, yb, xa, xb;
    float wya, wyb, wxa, wxb;
    if ((h & 1) == 0) { ya = max(iy - 1, 0);   yb = iy; wya = 0.25f; wyb = 0.75f; }
    else              { ya = iy; yb = min(iy + 1, 127); wya = 0.75f; wyb = 0.25f; }
    if ((w & 1) == 0) { xa = max(ix - 1, 0);   xb = ix; wxa = 0.25f; wxb = 0.75f; }
    else              { xa = ix; xb = min(ix + 1, 127); wxa = 0.75f; wxb = 0.25f; }

    const float* src;
    int cs, chout;
    float scale;
    if (ch < 32) { src = bfeat; cs = ch;      chout = 81 + ch;         scale = 1.f; }
    else         { src = bflow; cs = ch - 32; chout = 113 + (ch - 32); scale = 2.f; }

    const float* p = src + ((long)b * (ch < 32 ? 32 : 2) + cs) * 128 * 128;
    float v = wya * (wxa * p[ya * 128 + xa] + wxb * p[ya * 128 + xb])
            + wyb * (wxa * p[yb * 128 + xa] + wxb * p[yb * 128 + xb]);
    inp[((b * CIN0 + chout) * HH + h) * WW + w] = v * scale;
}

// ---------------------------------------------------------------------------
// conv3x3 32->32: ALL weights resident in smem (36KB), input tiles
// double-buffered via cp.async. 2 pixels/thread (rows ty, ty+16), f32x2 FMA.
// Dynamic smem: wall[32*9*32] + tiles[2][8*34*18]  = 76,032 B
// ---------------------------------------------------------------------------
#define C32_CK 8
#define C32_TILE (C32_CK * 34 * 18)        // 4896
#define C32_WALL (32 * 9 * 32)             // 9216
#define C32_SMEM ((C32_WALL + 2 * C32_TILE) * 4)

template <bool RES, bool LRELU_OUT>
__global__ __launch_bounds__(256, 2) void conv32_kernel(
    const float* __restrict__ in, const float* __restrict__ wts,
    const float* __restrict__ bias, const float* __restrict__ res,
    float* __restrict__ out)
{
    extern __shared__ float smem[];
    float* wall  = smem;                 // [ci][tap][o] -> 32*9*32
    float* tiles = smem + C32_WALL;      // 2 buffers of [cc][34][18]

    const int b  = blockIdx.z;
    const int h0 = blockIdx.y * 32, w0 = blockIdx.x * 16;
    const int tx = threadIdx.x, ty = threadIdx.y;
    const int tid = ty * 16 + tx;

    // --- prologue: async-load all weights (transposed) + tile chunk 0 ------
    for (int i = tid; i < C32_WALL; i += 256) {
        int ci  = i / 288;
        int rem = i % 288;
        int tap = rem / 32;
        int o   = rem % 32;
        cp_async4(smem_u32(&wall[i]), wts + (o * 32 + ci) * 9 + tap, true);
    }
    {
        float* t0 = tiles;
        for (int i = tid; i < C32_TILE; i += 256) {
            int cc  = i / 612;
            int rem = i % 612;
            int r = rem / 18, cl = rem % 18;
            int gy = h0 - 1 + r, gx = w0 - 1 + cl;
            bool ok = (gy >= 0 && gy < HH && gx >= 0 && gx < WW);
            const float* src = in + (((long)(b * 32 + cc) * HH + (ok ? gy : 0)) * WW + (ok ? gx : 0));
            cp_async4(smem_u32(&t0[i]), src, ok);
        }
    }
    cp_commit();

    unsigned long long accA[16], accB[16];
#pragma unroll
    for (int p = 0; p < 16; p++) {
        unsigned long long bv = pack2(bias[2 * p], bias[2 * p + 1]);
        accA[p] = bv;
        accB[p] = bv;
    }

    const int hA = h0 + ty, hB = h0 + ty + 16, w = w0 + tx;

    cp_wait0();
    __syncthreads();

    for (int chunk = 0; chunk < 4; chunk++) {
        const int c0 = chunk * C32_CK;
        float* cur = tiles + (chunk & 1) * C32_TILE;
        // prefetch next chunk
        if (chunk < 3) {
            float* nxt = tiles + ((chunk + 1) & 1) * C32_TILE;
            const int cn = (chunk + 1) * C32_CK;
            for (int i = tid; i < C32_TILE; i += 256) {
                int cc  = i / 612;
                int rem = i % 612;
                int r = rem / 18, cl = rem % 18;
                int gy = h0 - 1 + r, gx = w0 - 1 + cl;
                bool ok = (gy >= 0 && gy < HH && gx >= 0 && gx < WW);
                const float* src = in + (((long)(b * 32 + cn + cc) * HH + (ok ? gy : 0)) * WW + (ok ? gx : 0));
                cp_async4(smem_u32(&nxt[i]), src, ok);
            }
        }
        cp_commit();

#pragma unroll 2
        for (int cc = 0; cc < C32_CK; cc++) {
            const float* tbase = cur + cc * 612;
#pragma unroll
            for (int ky = 0; ky < 3; ky++) {
#pragma unroll
                for (int kx = 0; kx < 3; kx++) {
                    const int tap = ky * 3 + kx;
                    unsigned long long va = pack2dup(tbase[(ty + ky) * 18 + tx + kx]);
                    unsigned long long vb = pack2dup(tbase[(ty + 16 + ky) * 18 + tx + kx]);
                    const F4U2* wp = reinterpret_cast<const F4U2*>(
                        wall + ((c0 + cc) * 9 + tap) * 32);
#pragma unroll
                    for (int q = 0; q < 8; q++) {
                        F4U2 wv = wp[q];
                        accA[q * 2 + 0] = ffma2(va, wv.u[0], accA[q * 2 + 0]);
                        accA[q * 2 + 1] = ffma2(va, wv.u[1], accA[q * 2 + 1]);
                        accB[q * 2 + 0] = ffma2(vb, wv.u[0], accB[q * 2 + 0]);
                        accB[q * 2 + 1] = ffma2(vb, wv.u[1], accB[q * 2 + 1]);
                    }
                }
            }
        }

        cp_wait0();
        __syncthreads();
    }

#pragma unroll
    for (int p = 0; p < 16; p++) {
        float a0, a1, b0v, b1v;
        unpack2(accA[p], a0, a1);
        unpack2(accB[p], b0v, b1v);
        const int o0 = 2 * p, o1 = 2 * p + 1;
        long baseA0 = ((long)(b * 32 + o0) * HH + hA) * WW + w;
        long baseA1 = ((long)(b * 32 + o1) * HH + hA) * WW + w;
        long baseB0 = ((long)(b * 32 + o0) * HH + hB) * WW + w;
        long baseB1 = ((long)(b * 32 + o1) * HH + hB) * WW + w;
        if (RES) {
            a0  += res[baseA0]; a1  += res[baseA1];
            b0v += res[baseB0]; b1v += res[baseB1];
        }
        if (LRELU_OUT) {
            a0 = lrelu(a0); a1 = lrelu(a1);
            b0v = lrelu(b0v); b1v = lrelu(b1v);
        }
        out[baseA0] = a0;  out[baseA1] = a1;
        out[baseB0] = b0v; out[baseB1] = b1v;
    }
}

// ---------------------------------------------------------------------------
// conv0: 115 -> 32. Double-buffered tiles AND weight stages (CK=5), cp.async.
// Static smem: 2*(5*34*18) + 2*(5*9*32) = 9000 floats = 36 KB
// ---------------------------------------------------------------------------
#define C0_CK 5
#define C0_TILE (C0_CK * 34 * 18)          // 3060
#define C0_WCHK (C0_CK * 9 * 32)           // 1440

__global__ __launch_bounds__(256, 2) void conv0_kernel(
    const float* __restrict__ in, const float* __restrict__ wts,
    const float* __restrict__ bias, float* __restrict__ out)
{
    __shared__ __align__(16) float tiles[2][C0_TILE];
    __shared__ __align__(16) float wbuf[2][C0_WCHK];

    const int b  = blockIdx.z;
    const int h0 = blockIdx.y * 32, w0 = blockIdx.x * 16;
    const int tx = threadIdx.x, ty = threadIdx.y;
    const int tid = ty * 16 + tx;

    // prologue: chunk 0 tile + weights
    for (int i = tid; i < C0_TILE; i += 256) {
        int cc  = i / 612;
        int rem = i % 612;
        int r = rem / 18, cl = rem % 18;
        int gy = h0 - 1 + r, gx = w0 - 1 + cl;
        bool ok = (gy >= 0 && gy < HH && gx >= 0 && gx < WW);
        const float* src = in + (((long)(b * CIN0 + cc) * HH + (ok ? gy : 0)) * WW + (ok ? gx : 0));
        cp_async4(smem_u32(&tiles[0][i]), src, ok);
    }
    for (int i = tid; i < C0_WCHK; i += 256) {
        int cc  = i / 288;
        int rem = i % 288;
        int tap = rem / 32;
        int o   = rem % 32;
        cp_async4(smem_u32(&wbuf[0][i]), wts + (o * CIN0 + cc) * 9 + tap, true);
    }
    cp_commit();

    unsigned long long accA[16], accB[16];
#pragma unroll
    for (int p = 0; p < 16; p++) {
        unsigned long long bv = pack2(bias[2 * p], bias[2 * p + 1]);
        accA[p] = bv;
        accB[p] = bv;
    }

    const int hA = h0 + ty, hB = h0 + ty + 16, w = w0 + tx;

    cp_wait0();
    __syncthreads();

    for (int chunk = 0; chunk < 23; chunk++) {
        const float* cur = tiles[chunk & 1];
        const float* wc  = wbuf[chunk & 1];
        if (chunk < 22) {
            float* nt = tiles[(chunk + 1) & 1];
            float* nw = wbuf[(chunk + 1) & 1];
            const int cn = (chunk + 1) * C0_CK;
            for (int i = tid; i < C0_TILE; i += 256) {
                int cc  = i / 612;
                int rem = i % 612;
                int r = rem / 18, cl = rem % 18;
                int gy = h0 - 1 + r, gx = w0 - 1 + cl;
                bool ok = (gy >= 0 && gy < HH && gx >= 0 && gx < WW);
                const float* src = in + (((long)(b * CIN0 + cn + cc) * HH + (ok ? gy : 0)) * WW + (ok ? gx : 0));
                cp_async4(smem_u32(&nt[i]), src, ok);
            }
            for (int i = tid; i < C0_WCHK; i += 256) {
                int cc  = i / 288;
                int rem = i % 288;
                int tap = rem / 32;
                int o   = rem % 32;
                cp_async4(smem_u32(&nw[i]), wts + (o * CIN0 + cn + cc) * 9 + tap, true);
            }
        }
        cp_commit();

#pragma unroll
        for (int cc = 0; cc < C0_CK; cc++) {
            const float* tbase = cur + cc * 612;
#pragma unroll
            for (int ky = 0; ky < 3; ky++) {
#pragma unroll
                for (int kx = 0; kx < 3; kx++) {
                    const int tap = ky * 3 + kx;
                    unsigned long long va = pack2dup(tbase[(ty + ky) * 18 + tx + kx]);
                    unsigned long long vb = pack2dup(tbase[(ty + 16 + ky) * 18 + tx + kx]);
                    const F4U2* wp = reinterpret_cast<const F4U2*>(
                        wc + (cc * 9 + tap) * 32);
#pragma unroll
                    for (int q = 0; q < 8; q++) {
                        F4U2 wv = wp[q];
                        accA[q * 2 + 0] = ffma2(va, wv.u[0], accA[q * 2 + 0]);
                        accA[q * 2 + 1] = ffma2(va, wv.u[1], accA[q * 2 + 1]);
                        accB[q * 2 + 0] = ffma2(vb, wv.u[0], accB[q * 2 + 0]);
                        accB[q * 2 + 1] = ffma2(vb, wv.u[1], accB[q * 2 + 1]);
                    }
                }
            }
        }

        cp_wait0();
        __syncthreads();
    }

#pragma unroll
    for (int p = 0; p < 16; p++) {
        float a0, a1, b0v, b1v;
        unpack2(accA[p], a0, a1);
        unpack2(accB[p], b0v, b1v);
        const int o0 = 2 * p, o1 = 2 * p + 1;
        long baseA0 = ((long)(b * 32 + o0) * HH + hA) * WW + w;
        long baseA1 = ((long)(b * 32 + o1) * HH + hA) * WW + w;
        long baseB0 = ((long)(b * 32 + o0) * HH + hB) * WW + w;
        long baseB1 = ((long)(b * 32 + o1) * HH + hB) * WW + w;
        out[baseA0] = lrelu(a0);  out[baseA1] = lrelu(a1);
        out[baseB0] = lrelu(b0v); out[baseB1] = lrelu(b1v);
    }
}

// ---------------------------------------------------------------------------
// Final conv3x3 (32 -> 3) with fused split/stack/sigmoid epilogue.
// ---------------------------------------------------------------------------
__global__ __launch_bounds__(256) void convf_kernel(
    const float* __restrict__ feats, const float* __restrict__ wts,
    const float* __restrict__ bias, float* __restrict__ dout)
{
    const int b  = blockIdx.z;
    const int h0 = blockIdx.y * 16, w0 = blockIdx.x * 16;
    const int tx = threadIdx.x, ty = threadIdx.y;
    const int tid = ty * 16 + tx;

    __shared__ float tile[16][18][18];
    __shared__ float wsm[32][9][3];

    for (int i = tid; i < 32 * 9 * 3; i += 256) {
        int ci  = i / 27;
        int rem = i % 27;
        int tap = rem / 3;
        int o   = rem % 3;
        wsm[ci][tap][o] = wts[(o * 32 + ci) * 9 + tap];
    }

    float acc[3] = {bias[0], bias[1], bias[2]};
    const int h = h0 + ty, w = w0 + tx;

    for (int c0 = 0; c0 < 32; c0 += 16) {
        __syncthreads();
        for (int i = tid; i < 16 * 18 * 18; i += 256) {
            int cc  = i / 324;
            int rem = i % 324;
            int r = rem / 18, cl = rem % 18;
            int gy = h0 - 1 + r, gx = w0 - 1 + cl;
            float v = 0.f;
            if (gy >= 0 && gy < HH && gx >= 0 && gx < WW)
                v = feats[((b * 32 + c0 + cc) * HH + gy) * WW + gx];
            tile[cc][r][cl] = v;
        }
        __syncthreads();
#pragma unroll
        for (int cc = 0; cc < 16; cc++) {
#pragma unroll
            for (int tap = 0; tap < 9; tap++) {
                int ky = tap / 3, kx = tap % 3;
                float v = tile[cc][ty + ky][tx + kx];
                acc[0] += v * wsm[c0 + cc][tap][0];
                acc[1] += v * wsm[c0 + cc][tap][1];
                acc[2] += v * wsm[c0 + cc][tap][2];
            }
        }
    }

    const int pix = h * WW + w;
    dout[(b * 2 + 0) * HW + pix] = acc[0];
    dout[(b * 2 + 1) * HW + pix] = acc[1];
    float m = 1.f / (1.f + expf(-acc[2]));
    dout[BB * 2 * HW + b * HW + pix] = m;
}

// ---------------------------------------------------------------------------
// Launch
// ---------------------------------------------------------------------------
extern "C" void kernel_launch(void* const* d_in, const int* in_sizes, int n_in,
                              void* d_out, int out_size)
{
    const float* x_ref     = (const float*)d_in[0];
    const float* x_nb      = (const float*)d_in[1];
    const float* base_flow = (const float*)d_in[2];
    const float* base_feat = (const float*)d_in[3];
    const float* w0 = (const float*)d_in[4];
    const float* b0 = (const float*)d_in[5];
    const float* w1 = (const float*)d_in[6];
    const float* b1 = (const float*)d_in[7];
    const float* w2 = (const float*)d_in[8];
    const float* b2 = (const float*)d_in[9];
    const float* wf = (const float*)d_in[10];
    const float* bf = (const float*)d_in[11];

    float* inp;  cudaGetSymbolAddress((void**)&inp, g_inp);
    float* hbuf; cudaGetSymbolAddress((void**)&hbuf, g_h);
    float* tbuf; cudaGetSymbolAddress((void**)&tbuf, g_t);

    float* out   = (float*)d_out;
    float* feats = out + (BB * 2 * HW) + (BB * 1 * HW);

    cudaFuncSetAttribute(conv32_kernel<false, true>,
                         cudaFuncAttributeMaxDynamicSharedMemorySize, C32_SMEM);
    cudaFuncSetAttribute(conv32_kernel<true, true>,
                         cudaFuncAttributeMaxDynamicSharedMemorySize, C32_SMEM);

    dim3 blk(16, 16);
    dim3 grd16(WW / 16, HH / 16, BB);   // 16x16 pixel tiles
    dim3 grd32(WW / 16, HH / 32, BB);   // 16x32 pixel tiles (conv)

    corr_kernel<<<grd16, blk>>>(x_ref, x_nb, inp);
    upsample_kernel<<<(BB * 34 * HW) / 256, 256>>>(base_feat, base_flow, inp);
    conv0_kernel<<<grd32, blk>>>(inp, w0, b0, hbuf);
    conv32_kernel<false, true><<<grd32, blk, C32_SMEM>>>(hbuf, w1, b1, nullptr, tbuf);
    conv32_kernel<true,  true><<<grd32, blk, C32_SMEM>>>(tbuf, w2, b2, hbuf, feats);
    convf_kernel<<<grd16, blk>>>(feats, wf, bf, out);
}

// round 6
// speedup vs baseline: 2.5002x; 1.9137x over previous
#include <cuda_runtime.h>
#include <cuda_fp16.h>
#include <math.h>
#include <stdint.h>

#define BB 4
#define HH 256
#define WW 256
#define HW 65536

// fp16 channel-last activations
__device__ __half g_inp_t[BB * HW * 128];   // concat input (ch 0..114, pad->128)
__device__ __half g_h_t [BB * HW * 32];     // conv0 out
__device__ __half g_t1_t[BB * HW * 32];     // conv1 out
// precomputed mma.sync B fragments
__device__ uint2 g_w0f[72 * 128];           // conv0: KS=72
__device__ uint2 g_w1f[18 * 128];           // conv1: KS=18
__device__ uint2 g_w2f[18 * 128];           // conv2: KS=18

__device__ __forceinline__ float lrelu(float v) { return v >= 0.f ? v : 0.1f * v; }

__device__ __forceinline__ unsigned smem_u32(const void* p) {
    return (unsigned)__cvta_generic_to_shared(p);
}
__device__ __forceinline__ void cp_async16(unsigned dst, const void* src, bool p) {
    int sz = p ? 16 : 0;
    asm volatile("cp.async.cg.shared.global [%0], [%1], 16, %2;"
                 :: "r"(dst), "l"(src), "r"(sz));
}
__device__ __forceinline__ void cp_commit() { asm volatile("cp.async.commit_group;"); }
__device__ __forceinline__ void cp_wait0()  { asm volatile("cp.async.wait_group 0;"); }

#define LDSM_X4(r, addr) \
    asm volatile("ldmatrix.sync.aligned.m8n8.x4.shared.b16 {%0,%1,%2,%3}, [%4];" \
        : "=r"((r)[0]), "=r"((r)[1]), "=r"((r)[2]), "=r"((r)[3]) : "r"(addr))

#define MMA16816(c, a, bf) \
    asm volatile("mma.sync.aligned.m16n8k16.row.col.f32.f16.f16.f32 " \
        "{%0,%1,%2,%3}, {%4,%5,%6,%7}, {%8,%9}, {%0,%1,%2,%3};" \
        : "+f"((c)[0]), "+f"((c)[1]), "+f"((c)[2]), "+f"((c)[3]) \
        : "r"((a)[0]), "r"((a)[1]), "r"((a)[2]), "r"((a)[3]), \
          "r"((bf).x), "r"((bf).y))

// ===================== correlation =========================================
__global__ __launch_bounds__(256) void corr_kernel(
    const float* __restrict__ xref, const float* __restrict__ xnb,
    __half* __restrict__ inp_t)
{
    const int b  = blockIdx.z;
    const int h0 = blockIdx.y * 16, w0 = blockIdx.x * 16;
    const int tx = threadIdx.x, ty = threadIdx.y;
    const int tid = ty * 16 + tx;
    __shared__ float nb[8][24][24];

    float acc[81];
#pragma unroll
    for (int k = 0; k < 81; k++) acc[k] = 0.f;
    const int h = h0 + ty, w = w0 + tx;

    for (int c0 = 0; c0 < 32; c0 += 8) {
        for (int i = tid; i < 8 * 24 * 24; i += 256) {
            int cc = i / 576, rem = i % 576;
            int r = rem / 24, cl = rem % 24;
            int gy = h0 - 4 + r, gx = w0 - 4 + cl;
            float v = 0.f;
            if (gy >= 0 && gy < HH && gx >= 0 && gx < WW)
                v = xnb[((b * 32 + c0 + cc) * HH + gy) * WW + gx];
            nb[cc][r][cl] = v;
        }
        __syncthreads();
#pragma unroll
        for (int cc = 0; cc < 8; cc++) {
            float r = xref[((b * 32 + c0 + cc) * HH + h) * WW + w];
#pragma unroll
            for (int dy = 0; dy < 9; dy++)
#pragma unroll
                for (int dx = 0; dx < 9; dx++)
                    acc[dy * 9 + dx] += r * nb[cc][ty + dy][tx + dx];
        }
        __syncthreads();
    }

    __half2* op2 = (__half2*)(inp_t + ((size_t)(b * HW) + h * WW + w) * 128);
#pragma unroll
    for (int k = 0; k < 40; k++)
        op2[k] = __floats2half2_rn(lrelu(acc[2 * k] * (1.f / 32.f)),
                                   lrelu(acc[2 * k + 1] * (1.f / 32.f)));
    ((__half*)op2)[80] = __float2half_rn(lrelu(acc[80] * (1.f / 32.f)));
}

// ===================== upsample (ch 81..114, pads 115..127 = 0) ============
__global__ __launch_bounds__(256) void upsample_kernel(
    const float* __restrict__ bfeat, const float* __restrict__ bflow,
    __half* __restrict__ inp_t)
{
    int idx = blockIdx.x * 256 + threadIdx.x;
    if (idx >= BB * HW) return;
    int w = idx & 255, h = (idx >> 8) & 255, b = idx >> 16;

    int iy = h >> 1, ix = w >> 1;
    int ya, yb, xa, xb;
    float wya, wyb, wxa, wxb;
    if ((h & 1) == 0) { ya = max(iy - 1, 0);   yb = iy; wya = 0.25f; wyb = 0.75f; }
    else              { ya = iy; yb = min(iy + 1, 127); wya = 0.75f; wyb = 0.25f; }
    if ((w & 1) == 0) { xa = max(ix - 1, 0);   xb = ix; wxa = 0.25f; wxb = 0.75f; }
    else              { xa = ix; xb = min(ix + 1, 127); wxa = 0.75f; wxb = 0.25f; }

    __half* op = inp_t + (size_t)idx * 128;
    const float* fp = bfeat + (size_t)b * 32 * 16384;
#pragma unroll 4
    for (int c = 0; c < 32; c++) {
        const float* p = fp + c * 16384;
        float v = wya * (wxa * p[ya * 128 + xa] + wxb * p[ya * 128 + xb])
                + wyb * (wxa * p[yb * 128 + xa] + wxb * p[yb * 128 + xb]);
        op[81 + c] = __float2half_rn(v);
    }
    const float* lp = bflow + (size_t)b * 2 * 16384;
#pragma unroll
    for (int c = 0; c < 2; c++) {
        const float* p = lp + c * 16384;
        float v = wya * (wxa * p[ya * 128 + xa] + wxb * p[ya * 128 + xb])
                + wyb * (wxa * p[yb * 128 + xa] + wxb * p[yb * 128 + xb]);
        op[113 + c] = __float2half_rn(v * 2.f);
    }
#pragma unroll
    for (int c = 115; c < 128; c++) op[c] = __float2half_rn(0.f);
}

// ===================== B-fragment prep =====================================
// Fragment layout for mma.sync m16n8k16 row.col: for kstep ks, ntile nt, lane:
//   n = nt*8 + lane/4, q = lane%4
//   b0 = {B[ks*16+2q][n], B[ks*16+2q+1][n]}, b1 = same with k+8
// k decomposition: k = s*(3*CS) + kx*CS + c;  w layout [O][CIN][3][3]
template <int CIN, int CS>
__global__ void fprep_kernel(const float* __restrict__ w, uint2* __restrict__ dst)
{
    constexpr int KS = (9 * CS) / 16;
    int idx = blockIdx.x * 256 + threadIdx.x;
    if (idx >= KS * 4 * 32) return;
    int lane = idx & 31, nt = (idx >> 5) & 3, ks = idx >> 7;
    int n = nt * 8 + (lane >> 2), q = lane & 3;
    int k0 = ks * 16 + 2 * q;
    float v[4];
#pragma unroll
    for (int u = 0; u < 4; u++) {
        int k = k0 + (u >> 1) * 8 + (u & 1);
        int s = k / (3 * CS), r2 = k % (3 * CS), kx = r2 / CS, c = r2 % CS;
        v[u] = (c < CIN) ? w[((n * CIN + c) * 3 + s) * 3 + kx] : 0.f;
    }
    __half2 lo = __floats2half2_rn(v[0], v[1]);
    __half2 hi = __floats2half2_rn(v[2], v[3]);
    dst[idx] = make_uint2(*(uint32_t*)&lo, *(uint32_t*)&hi);
}

// ===================== conv3x3 via mma.sync (HMMA) =========================
// One CTA = one image row (256 pixels), 8 warps x 32 pixels.
// A[m=pixel][k=(kx,c)] from smem halo rows via ldmatrix; B frags from smem.
template <int CS, bool RES>
__global__ __launch_bounds__(256) void conv_hmma_kernel(
    const __half* __restrict__ act_in, const uint2* __restrict__ frags_g,
    const float* __restrict__ bias, const __half* __restrict__ res,
    __half* __restrict__ out16, float* __restrict__ outF32)
{
    constexpr int KSSTRIP = (3 * CS) / 16;       // 6 or 24
    constexpr int KS      = 3 * KSSTRIP;         // 18 or 72
    constexpr int ROWH    = CS + 8;              // padded row stride (halves)
    constexpr bool STAGE_ALL = (CS == 32);
    constexpr int NROWS   = STAGE_ALL ? 3 : 1;
    constexpr int STAGE_HALVES = NROWS * 258 * ROWH;
    constexpr int CPP     = CS / 8;              // 16B chunks per pixel

    extern __shared__ __align__(16) unsigned char smem_raw[];
    __half* stage = (__half*)smem_raw;
    uint2*  frags = (uint2*)(smem_raw + STAGE_HALVES * 2);

    const int tid = threadIdx.x;
    const int h = blockIdx.y, b = blockIdx.z;
    const int warp = tid >> 5, lane = tid & 31;
    const int wp0 = warp * 32;
    const int g = lane >> 2, q = lane & 3;

    // copy B fragments
    {
        const uint4* src = (const uint4*)frags_g;
        uint4* dst = (uint4*)frags;
        for (int i = tid; i < (KS * 4 * 32) / 2; i += 256)
            cp_async16(smem_u32(dst + i), src + i, true);
    }
    // stage strip(s)
    auto stage_strip = [&](int s, int slot) {
        int gy = h - 1 + s;
        bool rok = (gy >= 0 && gy < HH);
        const __half* rowp = act_in + ((size_t)(b * HW) + (rok ? gy : 0) * WW) * CS;
        for (int i = tid; i < 258 * CPP; i += 256) {
            int ph = i / CPP, cc = i % CPP;
            int gx = ph - 1;
            bool ok = rok && gx >= 0 && gx < WW;
            cp_async16(smem_u32(stage + (slot * 258 + ph) * ROWH + cc * 8),
                       rowp + (ok ? gx : 0) * CS + cc * 8, ok);
        }
    };
    if (STAGE_ALL) { stage_strip(0, 0); stage_strip(1, 1); stage_strip(2, 2); }
    else           { stage_strip(0, 0); }
    cp_commit(); cp_wait0();
    __syncthreads();

    float acc[2][4][4];
#pragma unroll
    for (int mt = 0; mt < 2; mt++)
#pragma unroll
        for (int nt = 0; nt < 4; nt++)
#pragma unroll
            for (int u = 0; u < 4; u++) acc[mt][nt][u] = 0.f;

    for (int s = 0; s < 3; s++) {
        if (!STAGE_ALL && s > 0) {
            __syncthreads();
            stage_strip(s, 0);
            cp_commit(); cp_wait0();
            __syncthreads();
        }
        const int slot = STAGE_ALL ? s : 0;
#pragma unroll 2
        for (int r = 0; r < KSSTRIP; r++) {
            const int kx = r / (CS / 16);
            const int c0 = (r % (CS / 16)) * 16;
            const int ksg = s * KSSTRIP + r;
            uint32_t a[2][4];
#pragma unroll
            for (int mt = 0; mt < 2; mt++) {
                int rowp = wp0 + mt * 16 + (lane & 15) + kx;
                uint32_t addr = smem_u32(
                    stage + (slot * 258 + rowp) * ROWH + c0 + ((lane >> 4) * 8));
                LDSM_X4(a[mt], addr);
            }
#pragma unroll
            for (int nt = 0; nt < 4; nt++) {
                uint2 bf = frags[(ksg * 4 + nt) * 32 + lane];
                MMA16816(acc[0][nt], a[0], bf);
                MMA16816(acc[1][nt], a[1], bf);
            }
        }
    }

    // epilogue
    const size_t rowbase = (size_t)(b * HW) + (size_t)h * WW;
#pragma unroll
    for (int mt = 0; mt < 2; mt++) {
#pragma unroll
        for (int nt = 0; nt < 4; nt++) {
            const int ch = nt * 8 + 2 * q;
            const float bz0 = __ldg(bias + ch), bz1 = __ldg(bias + ch + 1);
#pragma unroll
            for (int rr = 0; rr < 2; rr++) {
                const int p = wp0 + mt * 16 + g + rr * 8;
                float v0 = acc[mt][nt][rr * 2 + 0] + bz0;
                float v1 = acc[mt][nt][rr * 2 + 1] + bz1;
                const size_t pix = rowbase + p;
                if (RES) {
                    __half2 hv = *(const __half2*)(res + pix * 32 + ch);
                    v0 += __low2float(hv);
                    v1 += __high2float(hv);
                }
                v0 = lrelu(v0); v1 = lrelu(v1);
                if (out16)
                    *(__half2*)(out16 + pix * 32 + ch) = __floats2half2_rn(v0, v1);
                if (outF32) {
                    outF32[((size_t)(b * 32 + ch) * HH + h) * WW + p] = v0;
                    outF32[((size_t)(b * 32 + ch + 1) * HH + h) * WW + p] = v1;
                }
            }
        }
    }
}

// ===================== final conv 32->3 (fp32) =============================
__global__ __launch_bounds__(256) void convf_kernel(
    const float* __restrict__ feats, const float* __restrict__ wts,
    const float* __restrict__ bias, float* __restrict__ dout)
{
    const int b  = blockIdx.z;
    const int h0 = blockIdx.y * 16, w0 = blockIdx.x * 16;
    const int tx = threadIdx.x, ty = threadIdx.y;
    const int tid = ty * 16 + tx;
    __shared__ float tile[16][18][18];
    __shared__ float wsm[32][9][3];

    for (int i = tid; i < 32 * 9 * 3; i += 256) {
        int ci = i / 27, rem = i % 27;
        int tap = rem / 3, o = rem % 3;
        wsm[ci][tap][o] = wts[(o * 32 + ci) * 9 + tap];
    }
    float acc[3] = {bias[0], bias[1], bias[2]};
    const int h = h0 + ty, w = w0 + tx;

    for (int c0 = 0; c0 < 32; c0 += 16) {
        __syncthreads();
        for (int i = tid; i < 16 * 18 * 18; i += 256) {
            int cc = i / 324, rem = i % 324;
            int r = rem / 18, cl = rem % 18;
            int gy = h0 - 1 + r, gx = w0 - 1 + cl;
            float v = 0.f;
            if (gy >= 0 && gy < HH && gx >= 0 && gx < WW)
                v = feats[((b * 32 + c0 + cc) * HH + gy) * WW + gx];
            tile[cc][r][cl] = v;
        }
        __syncthreads();
#pragma unroll
        for (int cc = 0; cc < 16; cc++)
#pragma unroll
            for (int tap = 0; tap < 9; tap++) {
                float v = tile[cc][ty + tap / 3][tx + tap % 3];
                acc[0] += v * wsm[c0 + cc][tap][0];
                acc[1] += v * wsm[c0 + cc][tap][1];
                acc[2] += v * wsm[c0 + cc][tap][2];
            }
    }
    const int pix = h * WW + w;
    dout[(b * 2 + 0) * HW + pix] = acc[0];
    dout[(b * 2 + 1) * HW + pix] = acc[1];
    dout[BB * 2 * HW + b * HW + pix] = 1.f / (1.f + expf(-acc[2]));
}

// ===================== launch ==============================================
extern "C" void kernel_launch(void* const* d_in, const int* in_sizes, int n_in,
                              void* d_out, int out_size)
{
    const float* x_ref     = (const float*)d_in[0];
    const float* x_nb      = (const float*)d_in[1];
    const float* base_flow = (const float*)d_in[2];
    const float* base_feat = (const float*)d_in[3];
    const float* w0 = (const float*)d_in[4];
    const float* b0 = (const float*)d_in[5];
    const float* w1 = (const float*)d_in[6];
    const float* b1 = (const float*)d_in[7];
    const float* w2 = (const float*)d_in[8];
    const float* b2 = (const float*)d_in[9];
    const float* wf = (const float*)d_in[10];
    const float* bf = (const float*)d_in[11];

    __half *inp_t, *h_t, *t1_t;
    uint2 *w0f, *w1f, *w2f;
    cudaGetSymbolAddress((void**)&inp_t, g_inp_t);
    cudaGetSymbolAddress((void**)&h_t,  g_h_t);
    cudaGetSymbolAddress((void**)&t1_t, g_t1_t);
    cudaGetSymbolAddress((void**)&w0f, g_w0f);
    cudaGetSymbolAddress((void**)&w1f, g_w1f);
    cudaGetSymbolAddress((void**)&w2f, g_w2f);

    float* out   = (float*)d_out;
    float* feats = out + BB * 2 * HW + BB * HW;

    // dynamic smem: stage + fragments
    const int smem32 = (3 * 258 * 40) * 2 + 18 * 4 * 32 * 8;   // 80,352
    const int smem0  = (258 * 136) * 2 + 72 * 4 * 32 * 8;      // 143,904
    cudaFuncSetAttribute(conv_hmma_kernel<128, false>,
                         cudaFuncAttributeMaxDynamicSharedMemorySize, smem0);
    cudaFuncSetAttribute(conv_hmma_kernel<32, false>,
                         cudaFuncAttributeMaxDynamicSharedMemorySize, smem32);
    cudaFuncSetAttribute(conv_hmma_kernel<32, true>,
                         cudaFuncAttributeMaxDynamicSharedMemorySize, smem32);

    dim3 blk16(16, 16);
    dim3 grd16(WW / 16, HH / 16, BB);
    dim3 grdH(1, HH, BB);

    corr_kernel<<<grd16, blk16>>>(x_ref, x_nb, inp_t);
    upsample_kernel<<<(BB * HW) / 256, 256>>>(base_feat, base_flow, inp_t);
    fprep_kernel<115, 128><<<(72 * 128 + 255) / 256, 256>>>(w0, w0f);
    fprep_kernel<32, 32><<<(18 * 128 + 255) / 256, 256>>>(w1, w1f);
    fprep_kernel<32, 32><<<(18 * 128 + 255) / 256, 256>>>(w2, w2f);
    conv_hmma_kernel<128, false><<<grdH, 256, smem0>>>(inp_t, w0f, b0, nullptr, h_t, nullptr);
    conv_hmma_kernel<32, false><<<grdH, 256, smem32>>>(h_t, w1f, b1, nullptr, t1_t, nullptr);
    conv_hmma_kernel<32, true ><<<grdH, 256, smem32>>>(t1_t, w2f, b2, h_t, nullptr, feats);
    convf_kernel<<<grd16, blk16>>>(feats, wf, bf, out);
}

// round 7
// speedup vs baseline: 2.9118x; 1.1646x over previous
#include <cuda_runtime.h>
#include <cuda_fp16.h>
#include <math.h>
#include <stdint.h>

#define BB 4
#define HH 256
#define WW 256
#define HW 65536

// fp16 channel-last activations
__device__ __half g_inp_t[BB * HW * 128];   // concat input (ch 0..114, pad->128)
__device__ __half g_h_t [BB * HW * 32];     // conv0 out
__device__ __half g_t1_t[BB * HW * 32];     // conv1 out
__device__ __half g_f_t [BB * HW * 32];     // feats fp16 copy (for convf)
// precomputed mma.sync B fragments
__device__ uint2 g_w0f[72 * 128];           // conv0: KS=72, 4 ntiles
__device__ uint2 g_w1f[18 * 128];           // conv1
__device__ uint2 g_w2f[18 * 128];           // conv2
__device__ uint2 g_wff[18 * 32];            // convf: KS=18, 1 ntile (3 valid ch)

__device__ __forceinline__ float lrelu(float v) { return v >= 0.f ? v : 0.1f * v; }

__device__ __forceinline__ unsigned smem_u32(const void* p) {
    return (unsigned)__cvta_generic_to_shared(p);
}
__device__ __forceinline__ void cp_async16(unsigned dst, const void* src, bool p) {
    int sz = p ? 16 : 0;
    asm volatile("cp.async.cg.shared.global [%0], [%1], 16, %2;"
                 :: "r"(dst), "l"(src), "r"(sz));
}
__device__ __forceinline__ void cp_commit() { asm volatile("cp.async.commit_group;"); }
__device__ __forceinline__ void cp_wait0()  { asm volatile("cp.async.wait_group 0;"); }
__device__ __forceinline__ void cp_wait1()  { asm volatile("cp.async.wait_group 1;"); }

#define LDSM_X4(r, addr) \
    asm volatile("ldmatrix.sync.aligned.m8n8.x4.shared.b16 {%0,%1,%2,%3}, [%4];" \
        : "=r"((r)[0]), "=r"((r)[1]), "=r"((r)[2]), "=r"((r)[3]) : "r"(addr))

#define MMA16816(c, a, bf) \
    asm volatile("mma.sync.aligned.m16n8k16.row.col.f32.f16.f16.f32 " \
        "{%0,%1,%2,%3}, {%4,%5,%6,%7}, {%8,%9}, {%0,%1,%2,%3};" \
        : "+f"((c)[0]), "+f"((c)[1]), "+f"((c)[2]), "+f"((c)[3]) \
        : "r"((a)[0]), "r"((a)[1]), "r"((a)[2]), "r"((a)[3]), \
          "r"((bf).x), "r"((bf).y))

// ===================== correlation + upsample (merged) =====================
__global__ __launch_bounds__(256) void corr_up_kernel(
    const float* __restrict__ xref, const float* __restrict__ xnb,
    const float* __restrict__ bfeat, const float* __restrict__ bflow,
    __half* __restrict__ inp_t)
{
    const int b  = blockIdx.z;
    const int h0 = blockIdx.y * 16, w0 = blockIdx.x * 16;
    const int tx = threadIdx.x, ty = threadIdx.y;
    const int tid = ty * 16 + tx;
    __shared__ float nb[8][24][24];

    float acc[81];
#pragma unroll
    for (int k = 0; k < 81; k++) acc[k] = 0.f;
    const int h = h0 + ty, w = w0 + tx;

    for (int c0 = 0; c0 < 32; c0 += 8) {
        for (int i = tid; i < 8 * 24 * 24; i += 256) {
            int cc = i / 576, rem = i % 576;
            int r = rem / 24, cl = rem % 24;
            int gy = h0 - 4 + r, gx = w0 - 4 + cl;
            float v = 0.f;
            if (gy >= 0 && gy < HH && gx >= 0 && gx < WW)
                v = xnb[((b * 32 + c0 + cc) * HH + gy) * WW + gx];
            nb[cc][r][cl] = v;
        }
        __syncthreads();
#pragma unroll
        for (int cc = 0; cc < 8; cc++) {
            float r = xref[((b * 32 + c0 + cc) * HH + h) * WW + w];
#pragma unroll
            for (int dy = 0; dy < 9; dy++)
#pragma unroll
                for (int dx = 0; dx < 9; dx++)
                    acc[dy * 9 + dx] += r * nb[cc][ty + dy][tx + dx];
        }
        __syncthreads();
    }

    __half* op = inp_t + ((size_t)(b * HW) + h * WW + w) * 128;
    __half2* op2 = (__half2*)op;
#pragma unroll
    for (int k = 0; k < 40; k++)
        op2[k] = __floats2half2_rn(lrelu(acc[2 * k] * (1.f / 32.f)),
                                   lrelu(acc[2 * k + 1] * (1.f / 32.f)));
    op[80] = __float2half_rn(lrelu(acc[80] * (1.f / 32.f)));

    // ---- upsample channels 81..114 for this pixel (pads 115..127 = 0) ----
    {
        int iy = h >> 1, ix = w >> 1;
        int ya, yb, xa, xb;
        float wya, wyb, wxa, wxb;
        if ((h & 1) == 0) { ya = max(iy - 1, 0);   yb = iy; wya = 0.25f; wyb = 0.75f; }
        else              { ya = iy; yb = min(iy + 1, 127); wya = 0.75f; wyb = 0.25f; }
        if ((w & 1) == 0) { xa = max(ix - 1, 0);   xb = ix; wxa = 0.25f; wxb = 0.75f; }
        else              { xa = ix; xb = min(ix + 1, 127); wxa = 0.75f; wxb = 0.25f; }

        const float* fp = bfeat + (size_t)b * 32 * 16384;
#pragma unroll 4
        for (int c = 0; c < 32; c++) {
            const float* p = fp + c * 16384;
            float v = wya * (wxa * p[ya * 128 + xa] + wxb * p[ya * 128 + xb])
                    + wyb * (wxa * p[yb * 128 + xa] + wxb * p[yb * 128 + xb]);
            op[81 + c] = __float2half_rn(v);
        }
        const float* lp = bflow + (size_t)b * 2 * 16384;
#pragma unroll
        for (int c = 0; c < 2; c++) {
            const float* p = lp + c * 16384;
            float v = wya * (wxa * p[ya * 128 + xa] + wxb * p[ya * 128 + xb])
                    + wyb * (wxa * p[yb * 128 + xa] + wxb * p[yb * 128 + xb]);
            op[113 + c] = __float2half_rn(v * 2.f);
        }
#pragma unroll
        for (int c = 115; c < 128; c++) op[c] = __float2half_rn(0.f);
    }
}

// ===================== fused B-fragment prep ===============================
template <int CIN, int CS, int NTILES, int NOUT>
__device__ __forceinline__ void fprep_body(
    const float* __restrict__ w, uint2* __restrict__ dst, int idx)
{
    constexpr int KS = (9 * CS) / 16;
    if (idx >= KS * NTILES * 32) return;
    int lane = idx & 31;
    int nt = (idx >> 5) % NTILES;
    int ks = idx / (32 * NTILES);
    int n = nt * 8 + (lane >> 2), q = lane & 3;
    int k0 = ks * 16 + 2 * q;
    float v[4];
#pragma unroll
    for (int u = 0; u < 4; u++) {
        int k = k0 + (u >> 1) * 8 + (u & 1);
        int s = k / (3 * CS), r2 = k % (3 * CS), kx = r2 / CS, c = r2 % CS;
        v[u] = (c < CIN && n < NOUT) ? w[((n * CIN + c) * 3 + s) * 3 + kx] : 0.f;
    }
    __half2 lo = __floats2half2_rn(v[0], v[1]);
    __half2 hi = __floats2half2_rn(v[2], v[3]);
    dst[idx] = make_uint2(*(uint32_t*)&lo, *(uint32_t*)&hi);
}

__global__ __launch_bounds__(256) void fprep_all(
    const float* __restrict__ w0, const float* __restrict__ w1,
    const float* __restrict__ w2, const float* __restrict__ wf,
    uint2* __restrict__ d0, uint2* __restrict__ d1,
    uint2* __restrict__ d2, uint2* __restrict__ df)
{
    int blk = blockIdx.x;
    int t = threadIdx.x;
    if (blk < 36)      fprep_body<115, 128, 4, 32>(w0, d0, blk * 256 + t);
    else if (blk < 45) fprep_body<32, 32, 4, 32>(w1, d1, (blk - 36) * 256 + t);
    else if (blk < 54) fprep_body<32, 32, 4, 32>(w2, d2, (blk - 45) * 256 + t);
    else               fprep_body<32, 32, 1, 3>(wf, df, (blk - 54) * 256 + t);
}

// ===================== conv3x3 via mma.sync (HMMA) =========================
template <int CS, bool RES>
__global__ __launch_bounds__(256) void conv_hmma_kernel(
    const __half* __restrict__ act_in, const uint2* __restrict__ frags_g,
    const float* __restrict__ bias, const __half* __restrict__ res,
    __half* __restrict__ out16, float* __restrict__ outF32)
{
    constexpr int KSSTRIP = (3 * CS) / 16;
    constexpr int KS      = 3 * KSSTRIP;
    constexpr int ROWH    = CS + 8;
    constexpr bool STAGE_ALL = (CS == 32);
    constexpr int NROWS   = STAGE_ALL ? 3 : 2;
    constexpr int STAGE_HALVES = NROWS * 258 * ROWH;
    constexpr int CPP     = CS / 8;

    extern __shared__ __align__(16) unsigned char smem_raw[];
    __half* stage = (__half*)smem_raw;
    uint2*  frags = (uint2*)(smem_raw + STAGE_HALVES * 2);

    const int tid = threadIdx.x;
    const int h = blockIdx.y, b = blockIdx.z;
    const int warp = tid >> 5, lane = tid & 31;
    const int wp0 = warp * 32;
    const int g = lane >> 2, q = lane & 3;

    auto frag_copy = [&]() {
        const uint4* src = (const uint4*)frags_g;
        uint4* dst = (uint4*)frags;
        for (int i = tid; i < (KS * 4 * 32) / 2; i += 256)
            cp_async16(smem_u32(dst + i), src + i, true);
    };
    auto stage_strip = [&](int s, int slot) {
        int gy = h - 1 + s;
        bool rok = (gy >= 0 && gy < HH);
        const __half* rowp = act_in + ((size_t)(b * HW) + (rok ? gy : 0) * WW) * CS;
        for (int i = tid; i < 258 * CPP; i += 256) {
            int ph = i / CPP, cc = i % CPP;
            int gx = ph - 1;
            bool ok = rok && gx >= 0 && gx < WW;
            cp_async16(smem_u32(stage + (slot * 258 + ph) * ROWH + cc * 8),
                       rowp + (ok ? gx : 0) * CS + cc * 8, ok);
        }
    };

    float acc[2][4][4];
#pragma unroll
    for (int mt = 0; mt < 2; mt++)
#pragma unroll
        for (int nt = 0; nt < 4; nt++)
#pragma unroll
            for (int u = 0; u < 4; u++) acc[mt][nt][u] = 0.f;

    auto compute = [&](int s, int slot) {
#pragma unroll 2
        for (int r = 0; r < KSSTRIP; r++) {
            const int kx = r / (CS / 16);
            const int c0 = (r % (CS / 16)) * 16;
            const int ksg = s * KSSTRIP + r;
            uint32_t a[2][4];
#pragma unroll
            for (int mt = 0; mt < 2; mt++) {
                int rowp = wp0 + mt * 16 + (lane & 15) + kx;
                uint32_t addr = smem_u32(
                    stage + (slot * 258 + rowp) * ROWH + c0 + ((lane >> 4) * 8));
                LDSM_X4(a[mt], addr);
            }
#pragma unroll
            for (int nt = 0; nt < 4; nt++) {
                uint2 bf = frags[(ksg * 4 + nt) * 32 + lane];
                MMA16816(acc[0][nt], a[0], bf);
                MMA16816(acc[1][nt], a[1], bf);
            }
        }
    };

    if (STAGE_ALL) {
        frag_copy();
        stage_strip(0, 0); stage_strip(1, 1); stage_strip(2, 2);
        cp_commit(); cp_wait0();
        __syncthreads();
        compute(0, 0); compute(1, 1); compute(2, 2);
    } else {
        frag_copy(); stage_strip(0, 0); cp_commit();
        stage_strip(1, 1); cp_commit();
        cp_wait1(); __syncthreads();
        compute(0, 0);
        __syncthreads();
        stage_strip(2, 0); cp_commit();
        cp_wait1(); __syncthreads();
        compute(1, 1);
        cp_wait0(); __syncthreads();
        compute(2, 0);
    }

    const size_t rowbase = (size_t)(b * HW) + (size_t)h * WW;
#pragma unroll
    for (int mt = 0; mt < 2; mt++) {
#pragma unroll
        for (int nt = 0; nt < 4; nt++) {
            const int ch = nt * 8 + 2 * q;
            const float bz0 = __ldg(bias + ch), bz1 = __ldg(bias + ch + 1);
#pragma unroll
            for (int rr = 0; rr < 2; rr++) {
                const int p = wp0 + mt * 16 + g + rr * 8;
                float v0 = acc[mt][nt][rr * 2 + 0] + bz0;
                float v1 = acc[mt][nt][rr * 2 + 1] + bz1;
                const size_t pix = rowbase + p;
                if (RES) {
                    __half2 hv = *(const __half2*)(res + pix * 32 + ch);
                    v0 += __low2float(hv);
                    v1 += __high2float(hv);
                }
                v0 = lrelu(v0); v1 = lrelu(v1);
                if (out16)
                    *(__half2*)(out16 + pix * 32 + ch) = __floats2half2_rn(v0, v1);
                if (outF32) {
                    outF32[((size_t)(b * 32 + ch) * HH + h) * WW + p] = v0;
                    outF32[((size_t)(b * 32 + ch + 1) * HH + h) * WW + p] = v1;
                }
            }
        }
    }
}

// ===================== final conv 32->3 via HMMA ===========================
__global__ __launch_bounds__(256) void convf_hmma(
    const __half* __restrict__ feats16, const uint2* __restrict__ frags_g,
    const float* __restrict__ bias, float* __restrict__ dout)
{
    constexpr int KSSTRIP = 6, KS = 18, ROWH = 40, CPP = 4;
    extern __shared__ __align__(16) unsigned char smem_raw[];
    __half* stage = (__half*)smem_raw;
    uint2*  frags = (uint2*)(smem_raw + 3 * 258 * ROWH * 2);

    const int tid = threadIdx.x;
    const int h = blockIdx.y, b = blockIdx.z;
    const int warp = tid >> 5, lane = tid & 31;
    const int wp0 = warp * 32;
    const int g = lane >> 2, q = lane & 3;

    {
        const uint4* src = (const uint4*)frags_g;
        uint4* dst = (uint4*)frags;
        for (int i = tid; i < (KS * 32) / 2; i += 256)
            cp_async16(smem_u32(dst + i), src + i, true);
    }
    for (int s = 0; s < 3; s++) {
        int gy = h - 1 + s;
        bool rok = (gy >= 0 && gy < HH);
        const __half* rowp = feats16 + ((size_t)(b * HW) + (rok ? gy : 0) * WW) * 32;
        for (int i = tid; i < 258 * CPP; i += 256) {
            int ph = i / CPP, cc = i % CPP;
            int gx = ph - 1;
            bool ok = rok && gx >= 0 && gx < WW;
            cp_async16(smem_u32(stage + (s * 258 + ph) * ROWH + cc * 8),
                       rowp + (ok ? gx : 0) * 32 + cc * 8, ok);
        }
    }
    cp_commit(); cp_wait0();
    __syncthreads();

    float acc[2][4];
#pragma unroll
    for (int mt = 0; mt < 2; mt++)
#pragma unroll
        for (int u = 0; u < 4; u++) acc[mt][u] = 0.f;

    for (int s = 0; s < 3; s++) {
#pragma unroll
        for (int r = 0; r < KSSTRIP; r++) {
            const int kx = r / 2;
            const int c0 = (r % 2) * 16;
            const int ksg = s * KSSTRIP + r;
            uint32_t a[2][4];
#pragma unroll
            for (int mt = 0; mt < 2; mt++) {
                int rowp = wp0 + mt * 16 + (lane & 15) + kx;
                uint32_t addr = smem_u32(
                    stage + (s * 258 + rowp) * ROWH + c0 + ((lane >> 4) * 8));
                LDSM_X4(a[mt], addr);
            }
            uint2 bf = frags[ksg * 32 + lane];
            MMA16816(acc[0], a[0], bf);
            MMA16816(acc[1], a[1], bf);
        }
    }

    if (q == 0) {
        const float bz0 = __ldg(bias + 0), bz1 = __ldg(bias + 1);
#pragma unroll
        for (int mt = 0; mt < 2; mt++)
#pragma unroll
            for (int rr = 0; rr < 2; rr++) {
                const int p = wp0 + mt * 16 + g + rr * 8;
                const size_t pix = (size_t)h * WW + p;
                dout[(size_t)(b * 2 + 0) * HW + pix] = acc[mt][rr * 2 + 0] + bz0;
                dout[(size_t)(b * 2 + 1) * HW + pix] = acc[mt][rr * 2 + 1] + bz1;
            }
    } else if (q == 1) {
        const float bz2 = __ldg(bias + 2);
#pragma unroll
        for (int mt = 0; mt < 2; mt++)
#pragma unroll
            for (int rr = 0; rr < 2; rr++) {
                const int p = wp0 + mt * 16 + g + rr * 8;
                const size_t pix = (size_t)h * WW + p;
                float m = acc[mt][rr * 2 + 0] + bz2;
                dout[(size_t)(BB * 2) * HW + (size_t)b * HW + pix] =
                    1.f / (1.f + expf(-m));
            }
    }
}

// ===================== launch ==============================================
extern "C" void kernel_launch(void* const* d_in, const int* in_sizes, int n_in,
                              void* d_out, int out_size)
{
    const float* x_ref     = (const float*)d_in[0];
    const float* x_nb      = (const float*)d_in[1];
    const float* base_flow = (const float*)d_in[2];
    const float* base_feat = (const float*)d_in[3];
    const float* w0 = (const float*)d_in[4];
    const float* b0 = (const float*)d_in[5];
    const float* w1 = (const float*)d_in[6];
    const float* b1 = (const float*)d_in[7];
    const float* w2 = (const float*)d_in[8];
    const float* b2 = (const float*)d_in[9];
    const float* wf = (const float*)d_in[10];
    const float* bf = (const float*)d_in[11];

    __half *inp_t, *h_t, *t1_t, *f_t;
    uint2 *w0f, *w1f, *w2f, *wff;
    cudaGetSymbolAddress((void**)&inp_t, g_inp_t);
    cudaGetSymbolAddress((void**)&h_t,  g_h_t);
    cudaGetSymbolAddress((void**)&t1_t, g_t1_t);
    cudaGetSymbolAddress((void**)&f_t,  g_f_t);
    cudaGetSymbolAddress((void**)&w0f, g_w0f);
    cudaGetSymbolAddress((void**)&w1f, g_w1f);
    cudaGetSymbolAddress((void**)&w2f, g_w2f);
    cudaGetSymbolAddress((void**)&wff, g_wff);

    float* out   = (float*)d_out;
    float* feats = out + BB * 2 * HW + BB * HW;

    const int smem32 = (3 * 258 * 40) * 2 + 18 * 4 * 32 * 8;   // 80,352
    const int smem0  = (2 * 258 * 136) * 2 + 72 * 4 * 32 * 8;  // 214,080
    const int smemf  = (3 * 258 * 40) * 2 + 18 * 32 * 8;       // 66,528
    cudaFuncSetAttribute(conv_hmma_kernel<128, false>,
                         cudaFuncAttributeMaxDynamicSharedMemorySize, smem0);
    cudaFuncSetAttribute(conv_hmma_kernel<32, false>,
                         cudaFuncAttributeMaxDynamicSharedMemorySize, smem32);
    cudaFuncSetAttribute(conv_hmma_kernel<32, true>,
                         cudaFuncAttributeMaxDynamicSharedMemorySize, smem32);
    cudaFuncSetAttribute(convf_hmma,
                         cudaFuncAttributeMaxDynamicSharedMemorySize, smemf);

    dim3 blk16(16, 16);
    dim3 grd16(WW / 16, HH / 16, BB);
    dim3 grdH(1, HH, BB);

    corr_up_kernel<<<grd16, blk16>>>(x_ref, x_nb, base_feat, base_flow, inp_t);
    fprep_all<<<57, 256>>>(w0, w1, w2, wf, w0f, w1f, w2f, wff);
    conv_hmma_kernel<128, false><<<grdH, 256, smem0>>>(inp_t, w0f, b0, nullptr, h_t, nullptr);
    conv_hmma_kernel<32, false><<<grdH, 256, smem32>>>(h_t, w1f, b1, nullptr, t1_t, nullptr);
    conv_hmma_kernel<32, true ><<<grdH, 256, smem32>>>(t1_t, w2f, b2, h_t, f_t, feats);
    convf_hmma<<<grdH, 256, smemf>>>(f_t, wff, bf, out);
}

// round 8
// speedup vs baseline: 3.4757x; 1.1937x over previous
#include <cuda_runtime.h>
#include <cuda_fp16.h>
#include <math.h>
#include <stdint.h>

#define BB 4
#define HH 256
#define WW 256
#define HW 65536

// fp16 channel-last activations
__device__ __half g_inp_t[BB * HW * 128];   // concat input (ch 0..114, pad->128)
__device__ __half g_h_t [BB * HW * 32];     // conv0 out
__device__ __half g_t1_t[BB * HW * 32];     // conv1 out
__device__ __half g_f_t [BB * HW * 32];     // feats fp16 copy (for convf)
// precomputed mma.sync B fragments
__device__ uint2 g_w0f[72 * 128];           // conv0: KS=72, 4 ntiles
__device__ uint2 g_w1f[18 * 128];           // conv1
__device__ uint2 g_w2f[18 * 128];           // conv2
__device__ uint2 g_wff[18 * 32];            // convf: KS=18, 1 ntile (3 valid ch)

__device__ __forceinline__ float lrelu(float v) { return v >= 0.f ? v : 0.1f * v; }

__device__ __forceinline__ unsigned smem_u32(const void* p) {
    return (unsigned)__cvta_generic_to_shared(p);
}
__device__ __forceinline__ void cp_async16(unsigned dst, const void* src, bool p) {
    int sz = p ? 16 : 0;
    asm volatile("cp.async.cg.shared.global [%0], [%1], 16, %2;"
                 :: "r"(dst), "l"(src), "r"(sz));
}
__device__ __forceinline__ void cp_commit() { asm volatile("cp.async.commit_group;"); }
__device__ __forceinline__ void cp_wait0()  { asm volatile("cp.async.wait_group 0;"); }
__device__ __forceinline__ void cp_wait1()  { asm volatile("cp.async.wait_group 1;"); }

#define LDSM_X4(r, addr) \
    asm volatile("ldmatrix.sync.aligned.m8n8.x4.shared.b16 {%0,%1,%2,%3}, [%4];" \
        : "=r"((r)[0]), "=r"((r)[1]), "=r"((r)[2]), "=r"((r)[3]) : "r"(addr))

#define MMA16816(c, a, bf) \
    asm volatile("mma.sync.aligned.m16n8k16.row.col.f32.f16.f16.f32 " \
        "{%0,%1,%2,%3}, {%4,%5,%6,%7}, {%8,%9}, {%0,%1,%2,%3};" \
        : "+f"((c)[0]), "+f"((c)[1]), "+f"((c)[2]), "+f"((c)[3]) \
        : "r"((a)[0]), "r"((a)[1]), "r"((a)[2]), "r"((a)[3]), \
          "r"((bf).x), "r"((bf).y))

// ===================== correlation + upsample (merged) =====================
// block(32,8): one warp = one 32-pixel row -> conflict-free LDS.
// nb tile stored as half2 channel pairs -> half the LDS instructions.
__global__ __launch_bounds__(256) void corr_up_kernel(
    const float* __restrict__ xref, const float* __restrict__ xnb,
    const float* __restrict__ bfeat, const float* __restrict__ bflow,
    __half* __restrict__ inp_t)
{
    const int b  = blockIdx.z;
    const int h0 = blockIdx.y * 8, w0 = blockIdx.x * 32;
    const int tx = threadIdx.x, ty = threadIdx.y;   // (32,8)
    const int tid = ty * 32 + tx;

    __shared__ __half2 nb2[4][16][40];   // 4 ch-pairs, 16 halo rows, 40 halo cols

    float acc[81];
#pragma unroll
    for (int k = 0; k < 81; k++) acc[k] = 0.f;
    const int h = h0 + ty, w = w0 + tx;

    for (int c0 = 0; c0 < 32; c0 += 8) {
        // stage 8 channels as 4 half2 pairs over a 16x40 halo tile
        for (int i = tid; i < 4 * 16 * 40; i += 256) {
            int cc2 = i / 640, rem = i % 640;
            int r = rem / 40, cl = rem % 40;
            int gy = h0 - 4 + r, gx = w0 - 4 + cl;
            float v0 = 0.f, v1 = 0.f;
            if (gy >= 0 && gy < HH && gx >= 0 && gx < WW) {
                const float* p = xnb + ((size_t)(b * 32 + c0 + 2 * cc2) * HH + gy) * WW + gx;
                v0 = p[0];
                v1 = p[HW];
            }
            nb2[cc2][r][cl] = __floats2half2_rn(v0, v1);
        }
        __syncthreads();
#pragma unroll
        for (int cc2 = 0; cc2 < 4; cc2++) {
            const float rlo = xref[((size_t)(b * 32 + c0 + 2 * cc2) * HH + h) * WW + w];
            const float rhi = xref[((size_t)(b * 32 + c0 + 2 * cc2 + 1) * HH + h) * WW + w];
#pragma unroll
            for (int dy = 0; dy < 9; dy++)
#pragma unroll
                for (int dx = 0; dx < 9; dx++) {
                    float2 f = __half22float2(nb2[cc2][ty + dy][tx + dx]);
                    acc[dy * 9 + dx] += rlo * f.x + rhi * f.y;
                }
        }
        __syncthreads();
    }

    __half* op = inp_t + ((size_t)(b * HW) + h * WW + w) * 128;
    __half2* op2 = (__half2*)op;
#pragma unroll
    for (int k = 0; k < 40; k++)
        op2[k] = __floats2half2_rn(lrelu(acc[2 * k] * (1.f / 32.f)),
                                   lrelu(acc[2 * k + 1] * (1.f / 32.f)));
    op[80] = __float2half_rn(lrelu(acc[80] * (1.f / 32.f)));

    // ---- upsample channels 81..114 for this pixel (pads 115..127 = 0) ----
    {
        int iy = h >> 1, ix = w >> 1;
        int ya, yb, xa, xb;
        float wya, wyb, wxa, wxb;
        if ((h & 1) == 0) { ya = max(iy - 1, 0);   yb = iy; wya = 0.25f; wyb = 0.75f; }
        else              { ya = iy; yb = min(iy + 1, 127); wya = 0.75f; wyb = 0.25f; }
        if ((w & 1) == 0) { xa = max(ix - 1, 0);   xb = ix; wxa = 0.25f; wxb = 0.75f; }
        else              { xa = ix; xb = min(ix + 1, 127); wxa = 0.75f; wxb = 0.25f; }

        const float* fp = bfeat + (size_t)b * 32 * 16384;
#pragma unroll 4
        for (int c = 0; c < 32; c++) {
            const float* p = fp + c * 16384;
            float v = wya * (wxa * p[ya * 128 + xa] + wxb * p[ya * 128 + xb])
                    + wyb * (wxa * p[yb * 128 + xa] + wxb * p[yb * 128 + xb]);
            op[81 + c] = __float2half_rn(v);
        }
        const float* lp = bflow + (size_t)b * 2 * 16384;
#pragma unroll
        for (int c = 0; c < 2; c++) {
            const float* p = lp + c * 16384;
            float v = wya * (wxa * p[ya * 128 + xa] + wxb * p[ya * 128 + xb])
                    + wyb * (wxa * p[yb * 128 + xa] + wxb * p[yb * 128 + xb]);
            op[113 + c] = __float2half_rn(v * 2.f);
        }
#pragma unroll
        for (int c = 115; c < 128; c++) op[c] = __float2half_rn(0.f);
    }
}

// ===================== fused B-fragment prep ===============================
template <int CIN, int CS, int NTILES, int NOUT>
__device__ __forceinline__ void fprep_body(
    const float* __restrict__ w, uint2* __restrict__ dst, int idx)
{
    constexpr int KS = (9 * CS) / 16;
    if (idx >= KS * NTILES * 32) return;
    int lane = idx & 31;
    int nt = (idx >> 5) % NTILES;
    int ks = idx / (32 * NTILES);
    int n = nt * 8 + (lane >> 2), q = lane & 3;
    int k0 = ks * 16 + 2 * q;
    float v[4];
#pragma unroll
    for (int u = 0; u < 4; u++) {
        int k = k0 + (u >> 1) * 8 + (u & 1);
        int s = k / (3 * CS), r2 = k % (3 * CS), kx = r2 / CS, c = r2 % CS;
        v[u] = (c < CIN && n < NOUT) ? w[((n * CIN + c) * 3 + s) * 3 + kx] : 0.f;
    }
    __half2 lo = __floats2half2_rn(v[0], v[1]);
    __half2 hi = __floats2half2_rn(v[2], v[3]);
    dst[idx] = make_uint2(*(uint32_t*)&lo, *(uint32_t*)&hi);
}

__global__ __launch_bounds__(256) void fprep_all(
    const float* __restrict__ w0, const float* __restrict__ w1,
    const float* __restrict__ w2, const float* __restrict__ wf,
    uint2* __restrict__ d0, uint2* __restrict__ d1,
    uint2* __restrict__ d2, uint2* __restrict__ df)
{
    int blk = blockIdx.x;
    int t = threadIdx.x;
    if (blk < 36)      fprep_body<115, 128, 4, 32>(w0, d0, blk * 256 + t);
    else if (blk < 45) fprep_body<32, 32, 4, 32>(w1, d1, (blk - 36) * 256 + t);
    else if (blk < 54) fprep_body<32, 32, 4, 32>(w2, d2, (blk - 45) * 256 + t);
    else               fprep_body<32, 32, 1, 3>(wf, df, (blk - 54) * 256 + t);
}

// ===================== conv3x3 via mma.sync (HMMA) =========================
template <int CS, bool RES>
__global__ __launch_bounds__(256) void conv_hmma_kernel(
    const __half* __restrict__ act_in, const uint2* __restrict__ frags_g,
    const float* __restrict__ bias, const __half* __restrict__ res,
    __half* __restrict__ out16, float* __restrict__ outF32)
{
    constexpr int KSSTRIP = (3 * CS) / 16;
    constexpr int KS      = 3 * KSSTRIP;
    constexpr int ROWH    = CS + 8;
    constexpr bool STAGE_ALL = (CS == 32);
    constexpr int NROWS   = STAGE_ALL ? 3 : 2;
    constexpr int STAGE_HALVES = NROWS * 258 * ROWH;
    constexpr int CPP     = CS / 8;

    extern __shared__ __align__(16) unsigned char smem_raw[];
    __half* stage = (__half*)smem_raw;
    uint2*  frags = (uint2*)(smem_raw + STAGE_HALVES * 2);

    const int tid = threadIdx.x;
    const int h = blockIdx.y, b = blockIdx.z;
    const int warp = tid >> 5, lane = tid & 31;
    const int wp0 = warp * 32;
    const int g = lane >> 2, q = lane & 3;

    auto frag_copy = [&]() {
        const uint4* src = (const uint4*)frags_g;
        uint4* dst = (uint4*)frags;
        for (int i = tid; i < (KS * 4 * 32) / 2; i += 256)
            cp_async16(smem_u32(dst + i), src + i, true);
    };
    auto stage_strip = [&](int s, int slot) {
        int gy = h - 1 + s;
        bool rok = (gy >= 0 && gy < HH);
        const __half* rowp = act_in + ((size_t)(b * HW) + (rok ? gy : 0) * WW) * CS;
        for (int i = tid; i < 258 * CPP; i += 256) {
            int ph = i / CPP, cc = i % CPP;
            int gx = ph - 1;
            bool ok = rok && gx >= 0 && gx < WW;
            cp_async16(smem_u32(stage + (slot * 258 + ph) * ROWH + cc * 8),
                       rowp + (ok ? gx : 0) * CS + cc * 8, ok);
        }
    };

    float acc[2][4][4];
#pragma unroll
    for (int mt = 0; mt < 2; mt++)
#pragma unroll
        for (int nt = 0; nt < 4; nt++)
#pragma unroll
            for (int u = 0; u < 4; u++) acc[mt][nt][u] = 0.f;

    auto compute = [&](int s, int slot) {
#pragma unroll 2
        for (int r = 0; r < KSSTRIP; r++) {
            const int kx = r / (CS / 16);
            const int c0 = (r % (CS / 16)) * 16;
            const int ksg = s * KSSTRIP + r;
            uint32_t a[2][4];
#pragma unroll
            for (int mt = 0; mt < 2; mt++) {
                int rowp = wp0 + mt * 16 + (lane & 15) + kx;
                uint32_t addr = smem_u32(
                    stage + (slot * 258 + rowp) * ROWH + c0 + ((lane >> 4) * 8));
                LDSM_X4(a[mt], addr);
            }
#pragma unroll
            for (int nt = 0; nt < 4; nt++) {
                uint2 bf = frags[(ksg * 4 + nt) * 32 + lane];
                MMA16816(acc[0][nt], a[0], bf);
                MMA16816(acc[1][nt], a[1], bf);
            }
        }
    };

    if (STAGE_ALL) {
        frag_copy();
        stage_strip(0, 0); stage_strip(1, 1); stage_strip(2, 2);
        cp_commit(); cp_wait0();
        __syncthreads();
        compute(0, 0); compute(1, 1); compute(2, 2);
    } else {
        frag_copy(); stage_strip(0, 0); cp_commit();
        stage_strip(1, 1); cp_commit();
        cp_wait1(); __syncthreads();
        compute(0, 0);
        __syncthreads();
        stage_strip(2, 0); cp_commit();
        cp_wait1(); __syncthreads();
        compute(1, 1);
        cp_wait0(); __syncthreads();
        compute(2, 0);
    }

    const size_t rowbase = (size_t)(b * HW) + (size_t)h * WW;
#pragma unroll
    for (int mt = 0; mt < 2; mt++) {
#pragma unroll
        for (int nt = 0; nt < 4; nt++) {
            const int ch = nt * 8 + 2 * q;
            const float bz0 = __ldg(bias + ch), bz1 = __ldg(bias + ch + 1);
#pragma unroll
            for (int rr = 0; rr < 2; rr++) {
                const int p = wp0 + mt * 16 + g + rr * 8;
                float v0 = acc[mt][nt][rr * 2 + 0] + bz0;
                float v1 = acc[mt][nt][rr * 2 + 1] + bz1;
                const size_t pix = rowbase + p;
                if (RES) {
                    __half2 hv = *(const __half2*)(res + pix * 32 + ch);
                    v0 += __low2float(hv);
                    v1 += __high2float(hv);
                }
                v0 = lrelu(v0); v1 = lrelu(v1);
                if (out16)
                    *(__half2*)(out16 + pix * 32 + ch) = __floats2half2_rn(v0, v1);
                if (outF32) {
                    outF32[((size_t)(b * 32 + ch) * HH + h) * WW + p] = v0;
                    outF32[((size_t)(b * 32 + ch + 1) * HH + h) * WW + p] = v1;
                }
            }
        }
    }
}

// ===================== final conv 32->3 via HMMA ===========================
__global__ __launch_bounds__(256) void convf_hmma(
    const __half* __restrict__ feats16, const uint2* __restrict__ frags_g,
    const float* __restrict__ bias, float* __restrict__ dout)
{
    constexpr int KSSTRIP = 6, KS = 18, ROWH = 40, CPP = 4;
    extern __shared__ __align__(16) unsigned char smem_raw[];
    __half* stage = (__half*)smem_raw;
    uint2*  frags = (uint2*)(smem_raw + 3 * 258 * ROWH * 2);

    const int tid = threadIdx.x;
    const int h = blockIdx.y, b = blockIdx.z;
    const int warp = tid >> 5, lane = tid & 31;
    const int wp0 = warp * 32;
    const int g = lane >> 2, q = lane & 3;

    {
        const uint4* src = (const uint4*)frags_g;
        uint4* dst = (uint4*)frags;
        for (int i = tid; i < (KS * 32) / 2; i += 256)
            cp_async16(smem_u32(dst + i), src + i, true);
    }
    for (int s = 0; s < 3; s++) {
        int gy = h - 1 + s;
        bool rok = (gy >= 0 && gy < HH);
        const __half* rowp = feats16 + ((size_t)(b * HW) + (rok ? gy : 0) * WW) * 32;
        for (int i = tid; i < 258 * CPP; i += 256) {
            int ph = i / CPP, cc = i % CPP;
            int gx = ph - 1;
            bool ok = rok && gx >= 0 && gx < WW;
            cp_async16(smem_u32(stage + (s * 258 + ph) * ROWH + cc * 8),
                       rowp + (ok ? gx : 0) * 32 + cc * 8, ok);
        }
    }
    cp_commit(); cp_wait0();
    __syncthreads();

    float acc[2][4];
#pragma unroll
    for (int mt = 0; mt < 2; mt++)
#pragma unroll
        for (int u = 0; u < 4; u++) acc[mt][u] = 0.f;

    for (int s = 0; s < 3; s++) {
#pragma unroll
        for (int r = 0; r < KSSTRIP; r++) {
            const int kx = r / 2;
            const int c0 = (r % 2) * 16;
            const int ksg = s * KSSTRIP + r;
            uint32_t a[2][4];
#pragma unroll
            for (int mt = 0; mt < 2; mt++) {
                int rowp = wp0 + mt * 16 + (lane & 15) + kx;
                uint32_t addr = smem_u32(
                    stage + (s * 258 + rowp) * ROWH + c0 + ((lane >> 4) * 8));
                LDSM_X4(a[mt], addr);
            }
            uint2 bf = frags[ksg * 32 + lane];
            MMA16816(acc[0], a[0], bf);
            MMA16816(acc[1], a[1], bf);
        }
    }

    if (q == 0) {
        const float bz0 = __ldg(bias + 0), bz1 = __ldg(bias + 1);
#pragma unroll
        for (int mt = 0; mt < 2; mt++)
#pragma unroll
            for (int rr = 0; rr < 2; rr++) {
                const int p = wp0 + mt * 16 + g + rr * 8;
                const size_t pix = (size_t)h * WW + p;
                dout[(size_t)(b * 2 + 0) * HW + pix] = acc[mt][rr * 2 + 0] + bz0;
                dout[(size_t)(b * 2 + 1) * HW + pix] = acc[mt][rr * 2 + 1] + bz1;
            }
    } else if (q == 1) {
        const float bz2 = __ldg(bias + 2);
#pragma unroll
        for (int mt = 0; mt < 2; mt++)
#pragma unroll
            for (int rr = 0; rr < 2; rr++) {
                const int p = wp0 + mt * 16 + g + rr * 8;
                const size_t pix = (size_t)h * WW + p;
                float m = acc[mt][rr * 2 + 0] + bz2;
                dout[(size_t)(BB * 2) * HW + (size_t)b * HW + pix] =
                    1.f / (1.f + expf(-m));
            }
    }
}

// ===================== launch ==============================================
extern "C" void kernel_launch(void* const* d_in, const int* in_sizes, int n_in,
                              void* d_out, int out_size)
{
    const float* x_ref     = (const float*)d_in[0];
    const float* x_nb      = (const float*)d_in[1];
    const float* base_flow = (const float*)d_in[2];
    const float* base_feat = (const float*)d_in[3];
    const float* w0 = (const float*)d_in[4];
    const float* b0 = (const float*)d_in[5];
    const float* w1 = (const float*)d_in[6];
    const float* b1 = (const float*)d_in[7];
    const float* w2 = (const float*)d_in[8];
    const float* b2 = (const float*)d_in[9];
    const float* wf = (const float*)d_in[10];
    const float* bf = (const float*)d_in[11];

    __half *inp_t, *h_t, *t1_t, *f_t;
    uint2 *w0f, *w1f, *w2f, *wff;
    cudaGetSymbolAddress((void**)&inp_t, g_inp_t);
    cudaGetSymbolAddress((void**)&h_t,  g_h_t);
    cudaGetSymbolAddress((void**)&t1_t, g_t1_t);
    cudaGetSymbolAddress((void**)&f_t,  g_f_t);
    cudaGetSymbolAddress((void**)&w0f, g_w0f);
    cudaGetSymbolAddress((void**)&w1f, g_w1f);
    cudaGetSymbolAddress((void**)&w2f, g_w2f);
    cudaGetSymbolAddress((void**)&wff, g_wff);

    float* out   = (float*)d_out;
    float* feats = out + BB * 2 * HW + BB * HW;

    const int smem32 = (3 * 258 * 40) * 2 + 18 * 4 * 32 * 8;   // 80,352
    const int smem0  = (2 * 258 * 136) * 2 + 72 * 4 * 32 * 8;  // 214,080
    const int smemf  = (3 * 258 * 40) * 2 + 18 * 32 * 8;       // 66,528
    cudaFuncSetAttribute(conv_hmma_kernel<128, false>,
                         cudaFuncAttributeMaxDynamicSharedMemorySize, smem0);
    cudaFuncSetAttribute(conv_hmma_kernel<32, false>,
                         cudaFuncAttributeMaxDynamicSharedMemorySize, smem32);
    cudaFuncSetAttribute(conv_hmma_kernel<32, true>,
                         cudaFuncAttributeMaxDynamicSharedMemorySize, smem32);
    cudaFuncSetAttribute(convf_hmma,
                         cudaFuncAttributeMaxDynamicSharedMemorySize, smemf);

    dim3 blkC(32, 8);
    dim3 grdCorr(WW / 32, HH / 8, BB);
    dim3 grdH(1, HH, BB);

    corr_up_kernel<<<grdCorr, blkC>>>(x_ref, x_nb, base_feat, base_flow, inp_t);
    fprep_all<<<57, 256>>>(w0, w1, w2, wf, w0f, w1f, w2f, wff);
    conv_hmma_kernel<128, false><<<grdH, 256, smem0>>>(inp_t, w0f, b0, nullptr, h_t, nullptr);
    conv_hmma_kernel<32, false><<<grdH, 256, smem32>>>(h_t, w1f, b1, nullptr, t1_t, nullptr);
    conv_hmma_kernel<32, true ><<<grdH, 256, smem32>>>(t1_t, w2f, b2, h_t, f_t, feats);
    convf_hmma<<<grdH, 256, smemf>>>(f_t, wff, bf, out);
}